// round 2
// baseline (speedup 1.0000x reference)
#include <cuda_runtime.h>
#include <cuda_bf16.h>
#include <math.h>

// Problem constants (fixed by dataset)
#define BATCH 4
#define SEQ   1024
#define HEADS 16
#define HDIM  128
#define EMB   (HEADS * HDIM)        // 2048
#define TOTAL (BATCH * SEQ)         // 4096
#define E3    (3 * EMB)             // 6144

// Scratch (allocation-free rule: __device__ globals)
__device__ float g_qkv[(size_t)TOTAL * E3];   // 100.7 MB
__device__ float g_ctx[(size_t)TOTAL * EMB];  // 33.5 MB

// ---------------------------------------------------------------------------
// SGEMM: C[M,N] = A[M,K] @ B[K,N] + bias[N]   (all row-major fp32)
// BM=BN=128, BK=16, 256 threads, 8x8 microtile with strided mapping.
// ---------------------------------------------------------------------------
__global__ __launch_bounds__(256) void sgemm_bias_kernel(
    const float* __restrict__ A, const float* __restrict__ B,
    const float* __restrict__ bias, float* __restrict__ C,
    int M, int N, int K)
{
    __shared__ float As[16][132];   // padded (store-transpose conflict relief)
    __shared__ float Bs[16][128];

    const int tid = threadIdx.x;
    const int tx = tid & 15;
    const int ty = tid >> 4;
    const int m0 = blockIdx.y * 128;
    const int n0 = blockIdx.x * 128;

    float acc[8][8];
#pragma unroll
    for (int i = 0; i < 8; i++)
#pragma unroll
        for (int j = 0; j < 8; j++) acc[i][j] = 0.f;

    for (int k0 = 0; k0 < K; k0 += 16) {
        // Load A tile 128x16 (512 float4), store transposed As[k][m]
#pragma unroll
        for (int i = tid; i < 512; i += 256) {
            int r = i >> 2, c4 = i & 3;
            float4 v = *(const float4*)&A[(size_t)(m0 + r) * K + k0 + c4 * 4];
            As[c4 * 4 + 0][r] = v.x;
            As[c4 * 4 + 1][r] = v.y;
            As[c4 * 4 + 2][r] = v.z;
            As[c4 * 4 + 3][r] = v.w;
        }
        // Load B tile 16x128 (512 float4), row-major
#pragma unroll
        for (int i = tid; i < 512; i += 256) {
            int r = i >> 5, c4 = i & 31;
            *(float4*)&Bs[r][c4 * 4] =
                *(const float4*)&B[(size_t)(k0 + r) * N + n0 + c4 * 4];
        }
        __syncthreads();

#pragma unroll
        for (int k = 0; k < 16; k++) {
            float a[8], b[8];
#pragma unroll
            for (int i = 0; i < 8; i++) a[i] = As[k][ty + i * 16];
#pragma unroll
            for (int j = 0; j < 8; j++) b[j] = Bs[k][tx + j * 16];
#pragma unroll
            for (int i = 0; i < 8; i++)
#pragma unroll
                for (int j = 0; j < 8; j++) acc[i][j] += a[i] * b[j];
        }
        __syncthreads();
    }

#pragma unroll
    for (int i = 0; i < 8; i++) {
        int r = m0 + ty + i * 16;
#pragma unroll
        for (int j = 0; j < 8; j++) {
            int c = n0 + tx + j * 16;
            C[(size_t)r * N + c] = acc[i][j] + bias[c];
        }
    }
}

// ---------------------------------------------------------------------------
// Flash attention (causal), fp32, online softmax.
// One block per (q-tile of 64 rows, batch*head). 256 threads.
// Dynamic smem: Qs/Ks/Vs [64][132], Ss [64][65], m/l/alpha [64].
// ---------------------------------------------------------------------------
#define FA_BM 64
#define FA_BN 64
#define FA_PAD 132
#define FA_SMEM_FLOATS (3 * FA_BM * FA_PAD + FA_BM * 65 + 3 * FA_BM)
#define FA_SMEM_BYTES (FA_SMEM_FLOATS * 4)

__global__ __launch_bounds__(256) void flash_attn_kernel(
    const float* __restrict__ qkv, float* __restrict__ ctx)
{
    const int qt = blockIdx.x;            // 0..15
    const int bh = blockIdx.y;            // 0..63
    const int b  = bh / HEADS;
    const int h  = bh % HEADS;
    const int q0 = qt * FA_BM;
    const int tid = threadIdx.x;

    extern __shared__ float sm[];
    float* Qs   = sm;                         // [64][132]
    float* Ks   = Qs + FA_BM * FA_PAD;        // [64][132]
    float* Vs   = Ks + FA_BM * FA_PAD;        // [64][132]
    float* Ss   = Vs + FA_BM * FA_PAD;        // [64][65]
    float* mrow = Ss + FA_BM * 65;            // [64]
    float* lrow = mrow + FA_BM;               // [64]
    float* arow = lrow + FA_BM;               // [64]

    const float scale = 0.08838834764831845f; // 1/sqrt(128)

    // Load Q tile (q part of qkv: channel 0)
#pragma unroll
    for (int i = tid; i < FA_BM * 32; i += 256) {
        int r = i >> 5, c4 = i & 31;
        float4 v = *(const float4*)&qkv[(size_t)(b * SEQ + q0 + r) * E3 +
                                        h * HDIM + c4 * 4];
        *(float4*)&Qs[r * FA_PAD + c4 * 4] = v;
    }
    if (tid < FA_BM) { mrow[tid] = -INFINITY; lrow[tid] = 0.f; }

    // O accumulator: 4 rows x 8 dcols per thread
    const int rg = tid >> 4;   // 0..15 -> rows rg*4 .. rg*4+3
    const int dg = tid & 15;   // 0..15 -> cols dg*8 .. dg*8+7
    float oacc[4][8];
#pragma unroll
    for (int i = 0; i < 4; i++)
#pragma unroll
        for (int d = 0; d < 8; d++) oacc[i][d] = 0.f;

    const int tx = tid & 15;   // S-compute mapping
    const int ty = tid >> 4;

    const int ktiles = qt + 1; // causal: only tiles with k_start <= q_end

    for (int kt = 0; kt < ktiles; kt++) {
        const int k0 = kt * FA_BN;
        __syncthreads();   // previous iter done with Ks/Vs/Ss (and Q/m/l init)

        // Load K and V tiles (channels 1 and 2)
#pragma unroll
        for (int i = tid; i < FA_BN * 32; i += 256) {
            int r = i >> 5, c4 = i & 31;
            size_t base = (size_t)(b * SEQ + k0 + r) * E3 + h * HDIM + c4 * 4;
            *(float4*)&Ks[r * FA_PAD + c4 * 4] = *(const float4*)&qkv[base + EMB];
            *(float4*)&Vs[r * FA_PAD + c4 * 4] = *(const float4*)&qkv[base + 2 * EMB];
        }
        __syncthreads();

        // S = Q K^T * scale  -> Ss. 16x16 threads, 4x4 micro (strided).
        {
            float s[4][4];
#pragma unroll
            for (int i = 0; i < 4; i++)
#pragma unroll
                for (int j = 0; j < 4; j++) s[i][j] = 0.f;

            for (int d = 0; d < HDIM; d += 4) {
                float4 a[4], bb[4];
#pragma unroll
                for (int i = 0; i < 4; i++)
                    a[i] = *(const float4*)&Qs[(ty + i * 16) * FA_PAD + d];
#pragma unroll
                for (int j = 0; j < 4; j++)
                    bb[j] = *(const float4*)&Ks[(tx + j * 16) * FA_PAD + d];
#pragma unroll
                for (int i = 0; i < 4; i++)
#pragma unroll
                    for (int j = 0; j < 4; j++) {
                        s[i][j] += a[i].x * bb[j].x + a[i].y * bb[j].y +
                                   a[i].z * bb[j].z + a[i].w * bb[j].w;
                    }
            }
#pragma unroll
            for (int i = 0; i < 4; i++)
#pragma unroll
                for (int j = 0; j < 4; j++)
                    Ss[(ty + i * 16) * 65 + (tx + j * 16)] = s[i][j] * scale;
        }
        __syncthreads();

        // Softmax stats per row (threads 0..63), write P back into Ss.
        if (tid < FA_BM) {
            const int r = tid;
            const int qabs = q0 + r;
            int jmax = qabs - k0 + 1;          // #valid keys this tile
            if (jmax > FA_BN) jmax = FA_BN;
            float mx = -INFINITY;
            for (int j = 0; j < jmax; j++) {
                float v = Ss[r * 65 + j];
                mx = fmaxf(mx, v);
            }
            float mold = mrow[r];
            float mnew = fmaxf(mold, mx);
            float al = __expf(mold - mnew);    // 0 on first tile (mold=-inf)
            float sum = 0.f;
            for (int j = 0; j < FA_BN; j++) {
                float p = (j < jmax) ? __expf(Ss[r * 65 + j] - mnew) : 0.f;
                Ss[r * 65 + j] = p;
                sum += p;
            }
            lrow[r] = lrow[r] * al + sum;
            mrow[r] = mnew;
            arow[r] = al;
        }
        __syncthreads();

        // Rescale O and accumulate P @ V
        float alv[4];
#pragma unroll
        for (int i = 0; i < 4; i++) alv[i] = arow[rg * 4 + i];
#pragma unroll
        for (int i = 0; i < 4; i++)
#pragma unroll
            for (int d = 0; d < 8; d++) oacc[i][d] *= alv[i];

#pragma unroll 4
        for (int j = 0; j < FA_BN; j++) {
            float4 v0 = *(const float4*)&Vs[j * FA_PAD + dg * 8];
            float4 v1 = *(const float4*)&Vs[j * FA_PAD + dg * 8 + 4];
#pragma unroll
            for (int i = 0; i < 4; i++) {
                float p = Ss[(rg * 4 + i) * 65 + j];
                oacc[i][0] += p * v0.x;
                oacc[i][1] += p * v0.y;
                oacc[i][2] += p * v0.z;
                oacc[i][3] += p * v0.w;
                oacc[i][4] += p * v1.x;
                oacc[i][5] += p * v1.y;
                oacc[i][6] += p * v1.z;
                oacc[i][7] += p * v1.w;
            }
        }
    }

    // Epilogue: ctx[(b*S+q0+r)*E + h*D + d] = O / l
#pragma unroll
    for (int i = 0; i < 4; i++) {
        int r = rg * 4 + i;
        float inv = 1.f / lrow[r];
        float4 o0, o1;
        o0.x = oacc[i][0] * inv; o0.y = oacc[i][1] * inv;
        o0.z = oacc[i][2] * inv; o0.w = oacc[i][3] * inv;
        o1.x = oacc[i][4] * inv; o1.y = oacc[i][5] * inv;
        o1.z = oacc[i][6] * inv; o1.w = oacc[i][7] * inv;
        size_t base = (size_t)(b * SEQ + q0 + r) * EMB + h * HDIM + dg * 8;
        *(float4*)&g_ctx[base]     = o0;
        *(float4*)&g_ctx[base + 4] = o1;
    }
}

// ---------------------------------------------------------------------------
// Launch
// ---------------------------------------------------------------------------
extern "C" void kernel_launch(void* const* d_in, const int* in_sizes, int n_in,
                              void* d_out, int out_size)
{
    const float* hidden = (const float*)d_in[0];
    const float* wqkv   = (const float*)d_in[1];
    const float* bqkv   = (const float*)d_in[2];
    const float* wproj  = (const float*)d_in[3];
    const float* bproj  = (const float*)d_in[4];
    // d_in[5..8]: key_cache, value_cache, slots, seq_len -> dead w.r.t. output
    float* out = (float*)d_out;

    float* qkv_ptr;
    float* ctx_ptr;
    cudaGetSymbolAddress((void**)&qkv_ptr, g_qkv);
    cudaGetSymbolAddress((void**)&ctx_ptr, g_ctx);

    cudaFuncSetAttribute(flash_attn_kernel,
                         cudaFuncAttributeMaxDynamicSharedMemorySize,
                         FA_SMEM_BYTES);

    // 1) QKV GEMM: [4096,2048] @ [2048,6144] + bias
    {
        dim3 grid(E3 / 128, TOTAL / 128);
        sgemm_bias_kernel<<<grid, 256>>>(hidden, wqkv, bqkv, qkv_ptr,
                                         TOTAL, E3, EMB);
    }
    // 2) Flash attention -> ctx
    {
        dim3 grid(SEQ / FA_BM, BATCH * HEADS);
        flash_attn_kernel<<<grid, 256, FA_SMEM_BYTES>>>(qkv_ptr, ctx_ptr);
    }
    // 3) Proj GEMM: [4096,2048] @ [2048,2048] + bias -> out
    {
        dim3 grid(EMB / 128, TOTAL / 128);
        sgemm_bias_kernel<<<grid, 256>>>(ctx_ptr, wproj, bproj, out,
                                         TOTAL, EMB, EMB);
    }
}

// round 4
// speedup vs baseline: 2.2876x; 2.2876x over previous
#include <cuda_runtime.h>
#include <cuda_bf16.h>
#include <math.h>
#include <stdint.h>

// Problem constants (fixed by dataset)
#define BATCH 4
#define SEQ   1024
#define HEADS 16
#define HDIM  128
#define EMB   (HEADS * HDIM)        // 2048
#define TOTAL (BATCH * SEQ)         // 4096
#define E3    (3 * EMB)             // 6144

// ---------------------------------------------------------------------------
// Device scratch (allocation-free rule: __device__ globals)
// ---------------------------------------------------------------------------
__device__ float g_qkv[(size_t)TOTAL * E3];   // 100.7 MB
__device__ float g_ctx[(size_t)TOTAL * EMB];  // 33.5 MB

__device__ __nv_bfloat16 g_hid_hi[(size_t)TOTAL * EMB];
__device__ __nv_bfloat16 g_hid_lo[(size_t)TOTAL * EMB];
__device__ __nv_bfloat16 g_wqkvt_hi[(size_t)E3 * EMB];   // [N=6144, K=2048]
__device__ __nv_bfloat16 g_wqkvt_lo[(size_t)E3 * EMB];
__device__ __nv_bfloat16 g_wprojt_hi[(size_t)EMB * EMB]; // [N=2048, K=2048]
__device__ __nv_bfloat16 g_wprojt_lo[(size_t)EMB * EMB];
__device__ __nv_bfloat16 g_ctx_hi[(size_t)TOTAL * EMB];
__device__ __nv_bfloat16 g_ctx_lo[(size_t)TOTAL * EMB];

// ---------------------------------------------------------------------------
// PTX helpers (baseline compute_103-legal: ldmatrix / mma.sync / cp.async)
// ---------------------------------------------------------------------------
__device__ __forceinline__ uint32_t smem_u32(const void* p) {
    uint32_t a;
    asm("{ .reg .u64 t; cvta.to.shared.u64 t, %1; cvt.u32.u64 %0, t; }"
        : "=r"(a) : "l"(p));
    return a;
}
__device__ __forceinline__ void cp_async16(uint32_t dst, const void* src) {
    asm volatile("cp.async.cg.shared.global [%0], [%1], 16;"
                 :: "r"(dst), "l"(src) : "memory");
}
#define CP_COMMIT() asm volatile("cp.async.commit_group;" ::: "memory")
#define CP_WAIT(n)  asm volatile("cp.async.wait_group %0;" :: "n"(n) : "memory")

__device__ __forceinline__ void ldsm_x4(uint32_t* r, uint32_t addr) {
    asm volatile("ldmatrix.sync.aligned.m8n8.x4.shared.b16 {%0,%1,%2,%3}, [%4];"
                 : "=r"(r[0]), "=r"(r[1]), "=r"(r[2]), "=r"(r[3]) : "r"(addr));
}
__device__ __forceinline__ void mma_bf16(float* d, const uint32_t* a,
                                         const uint32_t* b) {
    asm volatile(
        "mma.sync.aligned.m16n8k16.row.col.f32.bf16.bf16.f32 "
        "{%0,%1,%2,%3}, {%4,%5,%6,%7}, {%8,%9}, {%0,%1,%2,%3};"
        : "+f"(d[0]), "+f"(d[1]), "+f"(d[2]), "+f"(d[3])
        : "r"(a[0]), "r"(a[1]), "r"(a[2]), "r"(a[3]), "r"(b[0]), "r"(b[1]));
}

// ---------------------------------------------------------------------------
// Split-convert: X (fp32) -> hi/lo bf16 (same layout)
// ---------------------------------------------------------------------------
__global__ void split_convert_kernel(const float* __restrict__ X,
                                     __nv_bfloat16* __restrict__ H,
                                     __nv_bfloat16* __restrict__ L, int n4)
{
    int i = blockIdx.x * blockDim.x + threadIdx.x;
    if (i >= n4) return;
    float4 v = ((const float4*)X)[i];
    float vs[4] = {v.x, v.y, v.z, v.w};
    __nv_bfloat16 h[4], l[4];
#pragma unroll
    for (int c = 0; c < 4; c++) {
        h[c] = __float2bfloat16(vs[c]);
        l[c] = __float2bfloat16(vs[c] - __bfloat162float(h[c]));
    }
    *(uint2*)(H + i * 4) = *(uint2*)h;
    *(uint2*)(L + i * 4) = *(uint2*)l;
}

// ---------------------------------------------------------------------------
// Transpose + split: X[K,N] fp32 row-major -> T[N,K] hi/lo bf16
// ---------------------------------------------------------------------------
__global__ void transpose_split_kernel(const float* __restrict__ X,
                                       __nv_bfloat16* __restrict__ TH,
                                       __nv_bfloat16* __restrict__ TL,
                                       int K, int N)
{
    __shared__ float tile[32][33];
    int n0 = blockIdx.x * 32, k0 = blockIdx.y * 32;
    int tx = threadIdx.x, ty = threadIdx.y;
#pragma unroll
    for (int i = 0; i < 4; i++)
        tile[ty + i * 8][tx] = X[(size_t)(k0 + ty + i * 8) * N + n0 + tx];
    __syncthreads();
#pragma unroll
    for (int i = 0; i < 4; i++) {
        int n = n0 + ty + i * 8;
        int k = k0 + tx;
        float v = tile[tx][ty + i * 8];
        __nv_bfloat16 hi = __float2bfloat16(v);
        __nv_bfloat16 lo = __float2bfloat16(v - __bfloat162float(hi));
        TH[(size_t)n * K + k] = hi;
        TL[(size_t)n * K + k] = lo;
    }
}

// ---------------------------------------------------------------------------
// bf16-split GEMM via mma.sync: C[M,N] = (Ahi+Alo) @ (Bhi+Blo)^T + bias
// A[M,K], B[N,K] row-major bf16. BM=BN=128, BK=32. 256 threads, 8 warps
// (2 in M x 4 in N), warp tile 64x32. cp.async double-buffered.
// Smem per stage: Ahi|Alo|Bhi|Blo, 8KB each (rows of 32 bf16 = 64B,
// 16B chunks XOR-swizzled: phys_c = c ^ ((row>>1)&3)).
// ---------------------------------------------------------------------------
#define GS_BUF   8192
#define GS_STAGE 32768
#define GSMEM_TOTAL (2 * GS_STAGE)

__device__ __forceinline__ void gemm_load_stage(
    uint32_t sbase, const __nv_bfloat16* __restrict__ Ahi,
    const __nv_bfloat16* __restrict__ Alo,
    const __nv_bfloat16* __restrict__ Bhi,
    const __nv_bfloat16* __restrict__ Blo,
    int m0, int n0, int K, int k0, int tid)
{
    const __nv_bfloat16* bufs[4] = {Ahi, Alo, Bhi, Blo};
#pragma unroll
    for (int i = 0; i < 8; i++) {
        const int buf = i >> 1;                       // 0..3
        const int cid = ((i & 1) << 8) + tid;         // 0..511
        const int r = cid >> 2;                       // 0..127
        const int c = cid & 3;                        // 16B chunk
        const int row = ((buf < 2) ? m0 : n0) + r;
        uint32_t dst = sbase + buf * GS_BUF + r * 64 +
                       ((c ^ ((r >> 1) & 3)) << 4);
        cp_async16(dst, bufs[buf] + (size_t)row * K + k0 + c * 8);
    }
}

__global__ __launch_bounds__(256) void gemm_mma_kernel(
    const __nv_bfloat16* __restrict__ Ahi, const __nv_bfloat16* __restrict__ Alo,
    const __nv_bfloat16* __restrict__ Bhi, const __nv_bfloat16* __restrict__ Blo,
    const float* __restrict__ bias, float* __restrict__ C,
    int M, int N, int K)
{
    extern __shared__ char smem[];
    const uint32_t sb = smem_u32(smem);
    const int tid = threadIdx.x;
    const int lane = tid & 31;
    const int wid = tid >> 5;
    const int warp_m = wid & 1;        // 0..1
    const int warp_n = wid >> 1;       // 0..3
    const int m0 = blockIdx.y * 128;
    const int n0 = blockIdx.x * 128;

    // ldmatrix lane decomposition
    const int sub = lane >> 3;         // 0..3 (which 8x8 tile)
    const int lane8 = lane & 7;
    // A: sub0: rows 0-7,c+0 | sub1: rows 8-15,c+0 | sub2: rows0-7,c+1 | sub3: rows8-15,c+1
    const int a_roff = ((sub & 1) << 3) + lane8;   // 0..15
    const int a_csub = sub >> 1;                   // 0..1
    // B: sub0: n0-7,c | sub1: n0-7,c+1 | sub2: n8-15,c | sub3: n8-15,c+1
    const int b_noff = (((sub >> 1) & 1) << 3) + lane8;
    const int b_csub = sub & 1;

    float acc[4][4][4];
#pragma unroll
    for (int i = 0; i < 4; i++)
#pragma unroll
        for (int j = 0; j < 4; j++)
#pragma unroll
            for (int k = 0; k < 4; k++) acc[i][j][k] = 0.f;

    const int NC = K / 32;
    gemm_load_stage(sb, Ahi, Alo, Bhi, Blo, m0, n0, K, 0, tid);
    CP_COMMIT();

    for (int c = 0; c < NC; c++) {
        if (c + 1 < NC) {
            gemm_load_stage(sb + ((c + 1) & 1) * GS_STAGE, Ahi, Alo, Bhi, Blo,
                            m0, n0, K, (c + 1) * 32, tid);
            CP_COMMIT();
            CP_WAIT(1);
        } else {
            CP_WAIT(0);
        }
        __syncthreads();

        const uint32_t st = sb + (c & 1) * GS_STAGE;
#pragma unroll
        for (int ks = 0; ks < 2; ks++) {
            uint32_t ah[4][4], al[4][4];
#pragma unroll
            for (int im = 0; im < 4; im++) {
                int r = warp_m * 64 + im * 16 + a_roff;
                int cc = ks * 2 + a_csub;
                uint32_t off = r * 64 + ((cc ^ ((r >> 1) & 3)) << 4);
                ldsm_x4(ah[im], st + off);
                ldsm_x4(al[im], st + GS_BUF + off);
            }
            uint32_t bh[4][2], bl[4][2];
#pragma unroll
            for (int in2 = 0; in2 < 2; in2++) {
                int n = warp_n * 32 + in2 * 16 + b_noff;
                int cc = ks * 2 + b_csub;
                uint32_t off = n * 64 + ((cc ^ ((n >> 1) & 3)) << 4);
                uint32_t t[4];
                ldsm_x4(t, st + 2 * GS_BUF + off);
                bh[in2 * 2][0] = t[0]; bh[in2 * 2][1] = t[1];
                bh[in2 * 2 + 1][0] = t[2]; bh[in2 * 2 + 1][1] = t[3];
                ldsm_x4(t, st + 3 * GS_BUF + off);
                bl[in2 * 2][0] = t[0]; bl[in2 * 2][1] = t[1];
                bl[in2 * 2 + 1][0] = t[2]; bl[in2 * 2 + 1][1] = t[3];
            }
#pragma unroll
            for (int im = 0; im < 4; im++)
#pragma unroll
                for (int in = 0; in < 4; in++) {
                    mma_bf16(acc[im][in], ah[im], bh[in]);
                    mma_bf16(acc[im][in], ah[im], bl[in]);
                    mma_bf16(acc[im][in], al[im], bh[in]);
                }
        }
        __syncthreads();
    }

    // Epilogue: fragment layout -> gmem, add bias
    const int groupID = lane >> 2;
    const int tig = lane & 3;
#pragma unroll
    for (int im = 0; im < 4; im++) {
        int row0 = m0 + warp_m * 64 + im * 16 + groupID;
#pragma unroll
        for (int in = 0; in < 4; in++) {
            int col = n0 + warp_n * 32 + in * 8 + tig * 2;
            float2 bv = *(const float2*)&bias[col];
            float2 o0, o1;
            o0.x = acc[im][in][0] + bv.x; o0.y = acc[im][in][1] + bv.y;
            o1.x = acc[im][in][2] + bv.x; o1.y = acc[im][in][3] + bv.y;
            *(float2*)&C[(size_t)row0 * N + col] = o0;
            *(float2*)&C[(size_t)(row0 + 8) * N + col] = o1;
        }
    }
}

// ---------------------------------------------------------------------------
// Flash attention (causal), fp32, online softmax. (unchanged — known good)
// ---------------------------------------------------------------------------
#define FA_BM 64
#define FA_BN 64
#define FA_PAD 132
#define FA_SMEM_FLOATS (3 * FA_BM * FA_PAD + FA_BM * 65 + 3 * FA_BM)
#define FA_SMEM_BYTES (FA_SMEM_FLOATS * 4)

__global__ __launch_bounds__(256) void flash_attn_kernel(
    const float* __restrict__ qkv, float* __restrict__ ctx)
{
    const int qt = blockIdx.x;
    const int bh = blockIdx.y;
    const int b  = bh / HEADS;
    const int h  = bh % HEADS;
    const int q0 = qt * FA_BM;
    const int tid = threadIdx.x;

    extern __shared__ float sm[];
    float* Qs   = sm;
    float* Ks   = Qs + FA_BM * FA_PAD;
    float* Vs   = Ks + FA_BM * FA_PAD;
    float* Ss   = Vs + FA_BM * FA_PAD;
    float* mrow = Ss + FA_BM * 65;
    float* lrow = mrow + FA_BM;
    float* arow = lrow + FA_BM;

    const float scale = 0.08838834764831845f;

#pragma unroll
    for (int i = tid; i < FA_BM * 32; i += 256) {
        int r = i >> 5, c4 = i & 31;
        float4 v = *(const float4*)&qkv[(size_t)(b * SEQ + q0 + r) * E3 +
                                        h * HDIM + c4 * 4];
        *(float4*)&Qs[r * FA_PAD + c4 * 4] = v;
    }
    if (tid < FA_BM) { mrow[tid] = -INFINITY; lrow[tid] = 0.f; }

    const int rg = tid >> 4;
    const int dg = tid & 15;
    float oacc[4][8];
#pragma unroll
    for (int i = 0; i < 4; i++)
#pragma unroll
        for (int d = 0; d < 8; d++) oacc[i][d] = 0.f;

    const int tx = tid & 15;
    const int ty = tid >> 4;
    const int ktiles = qt + 1;

    for (int kt = 0; kt < ktiles; kt++) {
        const int k0 = kt * FA_BN;
        __syncthreads();

#pragma unroll
        for (int i = tid; i < FA_BN * 32; i += 256) {
            int r = i >> 5, c4 = i & 31;
            size_t base = (size_t)(b * SEQ + k0 + r) * E3 + h * HDIM + c4 * 4;
            *(float4*)&Ks[r * FA_PAD + c4 * 4] = *(const float4*)&qkv[base + EMB];
            *(float4*)&Vs[r * FA_PAD + c4 * 4] = *(const float4*)&qkv[base + 2 * EMB];
        }
        __syncthreads();

        {
            float s[4][4];
#pragma unroll
            for (int i = 0; i < 4; i++)
#pragma unroll
                for (int j = 0; j < 4; j++) s[i][j] = 0.f;

            for (int d = 0; d < HDIM; d += 4) {
                float4 a[4], bb[4];
#pragma unroll
                for (int i = 0; i < 4; i++)
                    a[i] = *(const float4*)&Qs[(ty + i * 16) * FA_PAD + d];
#pragma unroll
                for (int j = 0; j < 4; j++)
                    bb[j] = *(const float4*)&Ks[(tx + j * 16) * FA_PAD + d];
#pragma unroll
                for (int i = 0; i < 4; i++)
#pragma unroll
                    for (int j = 0; j < 4; j++) {
                        s[i][j] += a[i].x * bb[j].x + a[i].y * bb[j].y +
                                   a[i].z * bb[j].z + a[i].w * bb[j].w;
                    }
            }
#pragma unroll
            for (int i = 0; i < 4; i++)
#pragma unroll
                for (int j = 0; j < 4; j++)
                    Ss[(ty + i * 16) * 65 + (tx + j * 16)] = s[i][j] * scale;
        }
        __syncthreads();

        if (tid < FA_BM) {
            const int r = tid;
            const int qabs = q0 + r;
            int jmax = qabs - k0 + 1;
            if (jmax > FA_BN) jmax = FA_BN;
            float mx = -INFINITY;
            for (int j = 0; j < jmax; j++) {
                float v = Ss[r * 65 + j];
                mx = fmaxf(mx, v);
            }
            float mold = mrow[r];
            float mnew = fmaxf(mold, mx);
            float al = __expf(mold - mnew);
            float sum = 0.f;
            for (int j = 0; j < FA_BN; j++) {
                float p = (j < jmax) ? __expf(Ss[r * 65 + j] - mnew) : 0.f;
                Ss[r * 65 + j] = p;
                sum += p;
            }
            lrow[r] = lrow[r] * al + sum;
            mrow[r] = mnew;
            arow[r] = al;
        }
        __syncthreads();

        float alv[4];
#pragma unroll
        for (int i = 0; i < 4; i++) alv[i] = arow[rg * 4 + i];
#pragma unroll
        for (int i = 0; i < 4; i++)
#pragma unroll
            for (int d = 0; d < 8; d++) oacc[i][d] *= alv[i];

#pragma unroll 4
        for (int j = 0; j < FA_BN; j++) {
            float4 v0 = *(const float4*)&Vs[j * FA_PAD + dg * 8];
            float4 v1 = *(const float4*)&Vs[j * FA_PAD + dg * 8 + 4];
#pragma unroll
            for (int i = 0; i < 4; i++) {
                float p = Ss[(rg * 4 + i) * 65 + j];
                oacc[i][0] += p * v0.x;
                oacc[i][1] += p * v0.y;
                oacc[i][2] += p * v0.z;
                oacc[i][3] += p * v0.w;
                oacc[i][4] += p * v1.x;
                oacc[i][5] += p * v1.y;
                oacc[i][6] += p * v1.z;
                oacc[i][7] += p * v1.w;
            }
        }
    }

#pragma unroll
    for (int i = 0; i < 4; i++) {
        int r = rg * 4 + i;
        float inv = 1.f / lrow[r];
        float4 o0, o1;
        o0.x = oacc[i][0] * inv; o0.y = oacc[i][1] * inv;
        o0.z = oacc[i][2] * inv; o0.w = oacc[i][3] * inv;
        o1.x = oacc[i][4] * inv; o1.y = oacc[i][5] * inv;
        o1.z = oacc[i][6] * inv; o1.w = oacc[i][7] * inv;
        size_t base = (size_t)(b * SEQ + q0 + r) * EMB + h * HDIM + dg * 8;
        *(float4*)&g_ctx[base]     = o0;
        *(float4*)&g_ctx[base + 4] = o1;
    }
}

// ---------------------------------------------------------------------------
// Launch
// ---------------------------------------------------------------------------
extern "C" void kernel_launch(void* const* d_in, const int* in_sizes, int n_in,
                              void* d_out, int out_size)
{
    const float* hidden = (const float*)d_in[0];
    const float* wqkv   = (const float*)d_in[1];
    const float* bqkv   = (const float*)d_in[2];
    const float* wproj  = (const float*)d_in[3];
    const float* bproj  = (const float*)d_in[4];
    float* out = (float*)d_out;

    float *qkv_ptr, *ctx_ptr;
    __nv_bfloat16 *hid_hi, *hid_lo, *wqkvt_hi, *wqkvt_lo;
    __nv_bfloat16 *wprojt_hi, *wprojt_lo, *ctx_hi, *ctx_lo;
    cudaGetSymbolAddress((void**)&qkv_ptr, g_qkv);
    cudaGetSymbolAddress((void**)&ctx_ptr, g_ctx);
    cudaGetSymbolAddress((void**)&hid_hi, g_hid_hi);
    cudaGetSymbolAddress((void**)&hid_lo, g_hid_lo);
    cudaGetSymbolAddress((void**)&wqkvt_hi, g_wqkvt_hi);
    cudaGetSymbolAddress((void**)&wqkvt_lo, g_wqkvt_lo);
    cudaGetSymbolAddress((void**)&wprojt_hi, g_wprojt_hi);
    cudaGetSymbolAddress((void**)&wprojt_lo, g_wprojt_lo);
    cudaGetSymbolAddress((void**)&ctx_hi, g_ctx_hi);
    cudaGetSymbolAddress((void**)&ctx_lo, g_ctx_lo);

    cudaFuncSetAttribute(flash_attn_kernel,
                         cudaFuncAttributeMaxDynamicSharedMemorySize,
                         FA_SMEM_BYTES);
    cudaFuncSetAttribute(gemm_mma_kernel,
                         cudaFuncAttributeMaxDynamicSharedMemorySize,
                         GSMEM_TOTAL);

    // 0) Split-convert hidden; transpose+split weights
    {
        int n4 = TOTAL * EMB / 4;
        split_convert_kernel<<<(n4 + 255) / 256, 256>>>(hidden, hid_hi, hid_lo, n4);
        dim3 blk(32, 8);
        transpose_split_kernel<<<dim3(E3 / 32, EMB / 32), blk>>>(
            wqkv, wqkvt_hi, wqkvt_lo, EMB, E3);
        transpose_split_kernel<<<dim3(EMB / 32, EMB / 32), blk>>>(
            wproj, wprojt_hi, wprojt_lo, EMB, EMB);
    }
    // 1) QKV GEMM (mma.sync): [4096,2048] @ [2048,6144] + bias
    {
        dim3 grid(E3 / 128, TOTAL / 128);
        gemm_mma_kernel<<<grid, 256, GSMEM_TOTAL>>>(
            hid_hi, hid_lo, wqkvt_hi, wqkvt_lo, bqkv, qkv_ptr,
            TOTAL, E3, EMB);
    }
    // 2) Flash attention -> ctx
    {
        dim3 grid(SEQ / FA_BM, BATCH * HEADS);
        flash_attn_kernel<<<grid, 256, FA_SMEM_BYTES>>>(qkv_ptr, ctx_ptr);
    }
    // 3) Split-convert ctx, then proj GEMM -> out
    {
        int n4 = TOTAL * EMB / 4;
        split_convert_kernel<<<(n4 + 255) / 256, 256>>>(ctx_ptr, ctx_hi, ctx_lo, n4);
        dim3 grid(EMB / 128, TOTAL / 128);
        gemm_mma_kernel<<<grid, 256, GSMEM_TOTAL>>>(
            ctx_hi, ctx_lo, wprojt_hi, wprojt_lo, bproj, out,
            TOTAL, EMB, EMB);
    }
}

// round 6
// speedup vs baseline: 3.5462x; 1.5502x over previous
#include <cuda_runtime.h>
#include <cuda_bf16.h>
#include <math.h>
#include <stdint.h>

// Problem constants (fixed by dataset)
#define BATCH 4
#define SEQ   1024
#define HEADS 16
#define HDIM  128
#define EMB   (HEADS * HDIM)        // 2048
#define TOTAL (BATCH * SEQ)         // 4096
#define E3    (3 * EMB)             // 6144

// ---------------------------------------------------------------------------
// Device scratch (allocation-free rule: __device__ globals)
// ---------------------------------------------------------------------------
__device__ __nv_bfloat16 g_hid_hi[(size_t)TOTAL * EMB];
__device__ __nv_bfloat16 g_hid_lo[(size_t)TOTAL * EMB];
__device__ __nv_bfloat16 g_wqkvt_hi[(size_t)E3 * EMB];   // [N=6144, K=2048]
__device__ __nv_bfloat16 g_wqkvt_lo[(size_t)E3 * EMB];
__device__ __nv_bfloat16 g_wprojt_hi[(size_t)EMB * EMB]; // [N=2048, K=2048]
__device__ __nv_bfloat16 g_wprojt_lo[(size_t)EMB * EMB];
__device__ __nv_bfloat16 g_qkv_hi[(size_t)TOTAL * E3];   // 50.3 MB
__device__ __nv_bfloat16 g_qkv_lo[(size_t)TOTAL * E3];
__device__ __nv_bfloat16 g_ctx_hi[(size_t)TOTAL * EMB];
__device__ __nv_bfloat16 g_ctx_lo[(size_t)TOTAL * EMB];

// ---------------------------------------------------------------------------
// PTX helpers (baseline compute_103-legal: ldmatrix / mma.sync / cp.async)
// ---------------------------------------------------------------------------
__device__ __forceinline__ uint32_t smem_u32(const void* p) {
    uint32_t a;
    asm("{ .reg .u64 t; cvta.to.shared.u64 t, %1; cvt.u32.u64 %0, t; }"
        : "=r"(a) : "l"(p));
    return a;
}
__device__ __forceinline__ void cp_async16(uint32_t dst, const void* src) {
    asm volatile("cp.async.cg.shared.global [%0], [%1], 16;"
                 :: "r"(dst), "l"(src) : "memory");
}
#define CP_COMMIT() asm volatile("cp.async.commit_group;" ::: "memory")
#define CP_WAIT(n)  asm volatile("cp.async.wait_group %0;" :: "n"(n) : "memory")

__device__ __forceinline__ void ldsm_x4(uint32_t* r, uint32_t addr) {
    asm volatile("ldmatrix.sync.aligned.m8n8.x4.shared.b16 {%0,%1,%2,%3}, [%4];"
                 : "=r"(r[0]), "=r"(r[1]), "=r"(r[2]), "=r"(r[3]) : "r"(addr));
}
__device__ __forceinline__ void ldsm_x4_t(uint32_t* r, uint32_t addr) {
    asm volatile("ldmatrix.sync.aligned.m8n8.x4.trans.shared.b16 {%0,%1,%2,%3}, [%4];"
                 : "=r"(r[0]), "=r"(r[1]), "=r"(r[2]), "=r"(r[3]) : "r"(addr));
}
__device__ __forceinline__ void mma_bf16(float* d, const uint32_t* a,
                                         const uint32_t* b) {
    asm volatile(
        "mma.sync.aligned.m16n8k16.row.col.f32.bf16.bf16.f32 "
        "{%0,%1,%2,%3}, {%4,%5,%6,%7}, {%8,%9}, {%0,%1,%2,%3};"
        : "+f"(d[0]), "+f"(d[1]), "+f"(d[2]), "+f"(d[3])
        : "r"(a[0]), "r"(a[1]), "r"(a[2]), "r"(a[3]), "r"(b[0]), "r"(b[1]));
}
__device__ __forceinline__ uint32_t pack_bf16(float x, float y) {
    __nv_bfloat162 t = __floats2bfloat162_rn(x, y);
    return *(uint32_t*)&t;
}

// ---------------------------------------------------------------------------
// Split-convert: X (fp32) -> hi/lo bf16 (same layout)
// ---------------------------------------------------------------------------
__global__ void split_convert_kernel(const float* __restrict__ X,
                                     __nv_bfloat16* __restrict__ H,
                                     __nv_bfloat16* __restrict__ L, int n4)
{
    int i = blockIdx.x * blockDim.x + threadIdx.x;
    if (i >= n4) return;
    float4 v = ((const float4*)X)[i];
    float vs[4] = {v.x, v.y, v.z, v.w};
    __nv_bfloat16 h[4], l[4];
#pragma unroll
    for (int c = 0; c < 4; c++) {
        h[c] = __float2bfloat16(vs[c]);
        l[c] = __float2bfloat16(vs[c] - __bfloat162float(h[c]));
    }
    *(uint2*)(H + i * 4) = *(uint2*)h;
    *(uint2*)(L + i * 4) = *(uint2*)l;
}

// ---------------------------------------------------------------------------
// Transpose + split: X[K,N] fp32 row-major -> T[N,K] hi/lo bf16
// ---------------------------------------------------------------------------
__global__ void transpose_split_kernel(const float* __restrict__ X,
                                       __nv_bfloat16* __restrict__ TH,
                                       __nv_bfloat16* __restrict__ TL,
                                       int K, int N)
{
    __shared__ float tile[32][33];
    int n0 = blockIdx.x * 32, k0 = blockIdx.y * 32;
    int tx = threadIdx.x, ty = threadIdx.y;
#pragma unroll
    for (int i = 0; i < 4; i++)
        tile[ty + i * 8][tx] = X[(size_t)(k0 + ty + i * 8) * N + n0 + tx];
    __syncthreads();
#pragma unroll
    for (int i = 0; i < 4; i++) {
        int n = n0 + ty + i * 8;
        int k = k0 + tx;
        float v = tile[tx][ty + i * 8];
        __nv_bfloat16 hi = __float2bfloat16(v);
        __nv_bfloat16 lo = __float2bfloat16(v - __bfloat162float(hi));
        TH[(size_t)n * K + k] = hi;
        TL[(size_t)n * K + k] = lo;
    }
}

// ---------------------------------------------------------------------------
// bf16-split GEMM via mma.sync: C = (Ahi+Alo) @ (Bhi+Blo)^T + bias
// A[M,K], B[N,K] row-major bf16. BM=BN=128, BK=32. 256 threads, 8 warps.
// mode 0: write fp32 Cf. mode 1: write split bf16 Ch/Cl.
// ---------------------------------------------------------------------------
#define GS_BUF   8192
#define GS_STAGE 32768
#define GSMEM_TOTAL (2 * GS_STAGE)

__device__ __forceinline__ void gemm_load_stage(
    uint32_t sbase, const __nv_bfloat16* __restrict__ Ahi,
    const __nv_bfloat16* __restrict__ Alo,
    const __nv_bfloat16* __restrict__ Bhi,
    const __nv_bfloat16* __restrict__ Blo,
    int m0, int n0, int K, int k0, int tid)
{
    const __nv_bfloat16* bufs[4] = {Ahi, Alo, Bhi, Blo};
#pragma unroll
    for (int i = 0; i < 8; i++) {
        const int buf = i >> 1;
        const int cid = ((i & 1) << 8) + tid;
        const int r = cid >> 2;
        const int c = cid & 3;
        const int row = ((buf < 2) ? m0 : n0) + r;
        uint32_t dst = sbase + buf * GS_BUF + r * 64 +
                       ((c ^ ((r >> 1) & 3)) << 4);
        cp_async16(dst, bufs[buf] + (size_t)row * K + k0 + c * 8);
    }
}

__global__ __launch_bounds__(256) void gemm_mma_kernel(
    const __nv_bfloat16* __restrict__ Ahi, const __nv_bfloat16* __restrict__ Alo,
    const __nv_bfloat16* __restrict__ Bhi, const __nv_bfloat16* __restrict__ Blo,
    const float* __restrict__ bias, float* __restrict__ Cf,
    __nv_bfloat16* __restrict__ Ch, __nv_bfloat16* __restrict__ Cl,
    int M, int N, int K, int mode)
{
    extern __shared__ char smem[];
    const uint32_t sb = smem_u32(smem);
    const int tid = threadIdx.x;
    const int lane = tid & 31;
    const int wid = tid >> 5;
    const int warp_m = wid & 1;
    const int warp_n = wid >> 1;
    const int m0 = blockIdx.y * 128;
    const int n0 = blockIdx.x * 128;

    const int sub = lane >> 3;
    const int lane8 = lane & 7;
    const int a_roff = ((sub & 1) << 3) + lane8;
    const int a_csub = sub >> 1;
    const int b_noff = (((sub >> 1) & 1) << 3) + lane8;
    const int b_csub = sub & 1;

    float acc[4][4][4];
#pragma unroll
    for (int i = 0; i < 4; i++)
#pragma unroll
        for (int j = 0; j < 4; j++)
#pragma unroll
            for (int k = 0; k < 4; k++) acc[i][j][k] = 0.f;

    const int NC = K / 32;
    gemm_load_stage(sb, Ahi, Alo, Bhi, Blo, m0, n0, K, 0, tid);
    CP_COMMIT();

    for (int c = 0; c < NC; c++) {
        if (c + 1 < NC) {
            gemm_load_stage(sb + ((c + 1) & 1) * GS_STAGE, Ahi, Alo, Bhi, Blo,
                            m0, n0, K, (c + 1) * 32, tid);
            CP_COMMIT();
            CP_WAIT(1);
        } else {
            CP_WAIT(0);
        }
        __syncthreads();

        const uint32_t st = sb + (c & 1) * GS_STAGE;
#pragma unroll
        for (int ks = 0; ks < 2; ks++) {
            uint32_t ah[4][4], al[4][4];
#pragma unroll
            for (int im = 0; im < 4; im++) {
                int r = warp_m * 64 + im * 16 + a_roff;
                int cc = ks * 2 + a_csub;
                uint32_t off = r * 64 + ((cc ^ ((r >> 1) & 3)) << 4);
                ldsm_x4(ah[im], st + off);
                ldsm_x4(al[im], st + GS_BUF + off);
            }
            uint32_t bh[4][2], bl[4][2];
#pragma unroll
            for (int in2 = 0; in2 < 2; in2++) {
                int n = warp_n * 32 + in2 * 16 + b_noff;
                int cc = ks * 2 + b_csub;
                uint32_t off = n * 64 + ((cc ^ ((n >> 1) & 3)) << 4);
                uint32_t t[4];
                ldsm_x4(t, st + 2 * GS_BUF + off);
                bh[in2 * 2][0] = t[0]; bh[in2 * 2][1] = t[1];
                bh[in2 * 2 + 1][0] = t[2]; bh[in2 * 2 + 1][1] = t[3];
                ldsm_x4(t, st + 3 * GS_BUF + off);
                bl[in2 * 2][0] = t[0]; bl[in2 * 2][1] = t[1];
                bl[in2 * 2 + 1][0] = t[2]; bl[in2 * 2 + 1][1] = t[3];
            }
#pragma unroll
            for (int im = 0; im < 4; im++)
#pragma unroll
                for (int in = 0; in < 4; in++) {
                    mma_bf16(acc[im][in], ah[im], bh[in]);
                    mma_bf16(acc[im][in], ah[im], bl[in]);
                    mma_bf16(acc[im][in], al[im], bh[in]);
                }
        }
        __syncthreads();
    }

    // Epilogue
    const int groupID = lane >> 2;
    const int tig = lane & 3;
#pragma unroll
    for (int im = 0; im < 4; im++) {
        int row0 = m0 + warp_m * 64 + im * 16 + groupID;
#pragma unroll
        for (int in = 0; in < 4; in++) {
            int col = n0 + warp_n * 32 + in * 8 + tig * 2;
            float2 bv = *(const float2*)&bias[col];
            float v00 = acc[im][in][0] + bv.x, v01 = acc[im][in][1] + bv.y;
            float v10 = acc[im][in][2] + bv.x, v11 = acc[im][in][3] + bv.y;
            if (mode == 0) {
                *(float2*)&Cf[(size_t)row0 * N + col] = make_float2(v00, v01);
                *(float2*)&Cf[(size_t)(row0 + 8) * N + col] = make_float2(v10, v11);
            } else {
                __nv_bfloat16 h00 = __float2bfloat16(v00);
                __nv_bfloat16 h01 = __float2bfloat16(v01);
                __nv_bfloat16 h10 = __float2bfloat16(v10);
                __nv_bfloat16 h11 = __float2bfloat16(v11);
                *(uint32_t*)&Ch[(size_t)row0 * N + col] =
                    pack_bf16(v00, v01);
                *(uint32_t*)&Ch[(size_t)(row0 + 8) * N + col] =
                    pack_bf16(v10, v11);
                *(uint32_t*)&Cl[(size_t)row0 * N + col] =
                    pack_bf16(v00 - __bfloat162float(h00),
                              v01 - __bfloat162float(h01));
                *(uint32_t*)&Cl[(size_t)(row0 + 8) * N + col] =
                    pack_bf16(v10 - __bfloat162float(h10),
                              v11 - __bfloat162float(h11));
            }
        }
    }
}

// ---------------------------------------------------------------------------
// Flash attention (causal) via mma.sync. BM=64 q rows, BN=64 keys, 4 warps.
// QK^T in bf16-hi (scores tiny -> rounding negligible); P@V with 3-product
// split (Phi*Vhi + Phi*Vlo + Plo*Vhi). Fragment-resident online softmax.
// Smem: Qs 16K | Ks 16K | Vh 16K | Vl 16K = 64KB. Row=256B, chunk swizzle
// phys_c = c ^ (r&7).
// ---------------------------------------------------------------------------
#define AT_SMEM 65536

__global__ __launch_bounds__(128) void flash_attn_mma_kernel(
    const __nv_bfloat16* __restrict__ qkv_hi,
    const __nv_bfloat16* __restrict__ qkv_lo,
    __nv_bfloat16* __restrict__ ctx_hi,
    __nv_bfloat16* __restrict__ ctx_lo)
{
    extern __shared__ char smem[];
    const uint32_t sb = smem_u32(smem);
    const uint32_t Qs = sb;
    const uint32_t Ks = sb + 16384;
    const uint32_t Vh = sb + 32768;
    const uint32_t Vl = sb + 49152;

    const int qt = blockIdx.x;            // 0..15
    const int bh = blockIdx.y;            // 0..63
    const int b = bh >> 4, h = bh & 15;
    const int q0 = qt * 64;
    const int tid = threadIdx.x;
    const int lane = tid & 31;
    const int w = tid >> 5;

    const int sub = lane >> 3, lane8 = lane & 7;
    const int a_roff = ((sub & 1) << 3) + lane8;
    const int a_csub = sub >> 1;
    const int b_noff = (((sub >> 1) & 1) << 3) + lane8;
    const int b_csub = sub & 1;
    const int g = lane >> 2, tig = lane & 3;

    const size_t tok0 = (size_t)b * SEQ + q0;

    // Q tile (hi) async load
#pragma unroll
    for (int i = 0; i < 8; i++) {
        int idx = tid + i * 128;
        int r = idx >> 4, c = idx & 15;
        uint32_t dst = Qs + r * 256 + ((c ^ (r & 7)) << 4);
        cp_async16(dst, qkv_hi + (tok0 + r) * E3 + h * HDIM + c * 8);
    }
    // K/V tile 0
    {
        size_t kb0 = (size_t)b * SEQ;
#pragma unroll
        for (int i = 0; i < 8; i++) {
            int idx = tid + i * 128;
            int r = idx >> 4, c = idx & 15;
            uint32_t sw = r * 256 + ((c ^ (r & 7)) << 4);
            size_t base = (kb0 + r) * E3 + h * HDIM + c * 8;
            cp_async16(Ks + sw, qkv_hi + base + EMB);
            cp_async16(Vh + sw, qkv_hi + base + 2 * EMB);
            cp_async16(Vl + sw, qkv_lo + base + 2 * EMB);
        }
    }
    CP_COMMIT(); CP_WAIT(0); __syncthreads();

    // Q fragments in registers for whole kernel
    uint32_t qa[8][4];
#pragma unroll
    for (int kc = 0; kc < 8; kc++) {
        int r = w * 16 + a_roff;
        int c = kc * 2 + a_csub;
        ldsm_x4(qa[kc], Qs + r * 256 + ((c ^ (r & 7)) << 4));
    }

    float oacc[16][4];
#pragma unroll
    for (int t = 0; t < 16; t++)
#pragma unroll
        for (int k = 0; k < 4; k++) oacc[t][k] = 0.f;
    float m0 = -INFINITY, m1 = -INFINITY, l0 = 0.f, l1 = 0.f;

    const float sc = 0.08838834764831845f;
    const int row0 = q0 + w * 16 + g;
    const int row1 = row0 + 8;

    for (int kt = 0; kt <= qt; kt++) {
        if (kt > 0) {
            __syncthreads();   // done with previous K/V smem
            size_t kb0 = (size_t)b * SEQ + kt * 64;
#pragma unroll
            for (int i = 0; i < 8; i++) {
                int idx = tid + i * 128;
                int r = idx >> 4, c = idx & 15;
                uint32_t sw = r * 256 + ((c ^ (r & 7)) << 4);
                size_t base = (kb0 + r) * E3 + h * HDIM + c * 8;
                cp_async16(Ks + sw, qkv_hi + base + EMB);
                cp_async16(Vh + sw, qkv_hi + base + 2 * EMB);
                cp_async16(Vl + sw, qkv_lo + base + 2 * EMB);
            }
            CP_COMMIT(); CP_WAIT(0); __syncthreads();
        }

        // S = Q K^T (hi only)
        float sacc[8][4];
#pragma unroll
        for (int j = 0; j < 8; j++)
#pragma unroll
            for (int k = 0; k < 4; k++) sacc[j][k] = 0.f;
#pragma unroll
        for (int kc = 0; kc < 8; kc++) {
#pragma unroll
            for (int jn = 0; jn < 4; jn++) {
                int r = jn * 16 + b_noff;
                int c = kc * 2 + b_csub;
                uint32_t kb[4];
                ldsm_x4(kb, Ks + r * 256 + ((c ^ (r & 7)) << 4));
                mma_bf16(sacc[jn * 2],     qa[kc], kb);
                mma_bf16(sacc[jn * 2 + 1], qa[kc], kb + 2);
            }
        }

        // scale + causal mask + row max
        float mx0 = -INFINITY, mx1 = -INFINITY;
#pragma unroll
        for (int j = 0; j < 8; j++) {
            int col = kt * 64 + j * 8 + tig * 2;
            float s0 = sacc[j][0] * sc, s1 = sacc[j][1] * sc;
            float s2 = sacc[j][2] * sc, s3 = sacc[j][3] * sc;
            if (kt == qt) {
                if (col > row0)     s0 = -1e30f;
                if (col + 1 > row0) s1 = -1e30f;
                if (col > row1)     s2 = -1e30f;
                if (col + 1 > row1) s3 = -1e30f;
            }
            sacc[j][0] = s0; sacc[j][1] = s1; sacc[j][2] = s2; sacc[j][3] = s3;
            mx0 = fmaxf(mx0, fmaxf(s0, s1));
            mx1 = fmaxf(mx1, fmaxf(s2, s3));
        }
        mx0 = fmaxf(mx0, __shfl_xor_sync(0xffffffffu, mx0, 1));
        mx0 = fmaxf(mx0, __shfl_xor_sync(0xffffffffu, mx0, 2));
        mx1 = fmaxf(mx1, __shfl_xor_sync(0xffffffffu, mx1, 1));
        mx1 = fmaxf(mx1, __shfl_xor_sync(0xffffffffu, mx1, 2));

        float mn0 = fmaxf(m0, mx0), mn1 = fmaxf(m1, mx1);
        float al0 = __expf(m0 - mn0), al1 = __expf(m1 - mn1);
        m0 = mn0; m1 = mn1;

        float sum0 = 0.f, sum1 = 0.f;
#pragma unroll
        for (int j = 0; j < 8; j++) {
            float p0 = __expf(sacc[j][0] - mn0);
            float p1 = __expf(sacc[j][1] - mn0);
            float p2 = __expf(sacc[j][2] - mn1);
            float p3 = __expf(sacc[j][3] - mn1);
            sacc[j][0] = p0; sacc[j][1] = p1; sacc[j][2] = p2; sacc[j][3] = p3;
            sum0 += p0 + p1; sum1 += p2 + p3;
        }
        sum0 += __shfl_xor_sync(0xffffffffu, sum0, 1);
        sum0 += __shfl_xor_sync(0xffffffffu, sum0, 2);
        sum1 += __shfl_xor_sync(0xffffffffu, sum1, 1);
        sum1 += __shfl_xor_sync(0xffffffffu, sum1, 2);
        l0 = l0 * al0 + sum0;
        l1 = l1 * al1 + sum1;

        // rescale O
#pragma unroll
        for (int t = 0; t < 16; t++) {
            oacc[t][0] *= al0; oacc[t][1] *= al0;
            oacc[t][2] *= al1; oacc[t][3] *= al1;
        }

        // pack P fragments (hi/lo split)
        uint32_t phi[4][4], plo[4][4];
#pragma unroll
        for (int kc = 0; kc < 4; kc++) {
            int t0 = kc * 2, t1 = kc * 2 + 1;
            float p[8] = { sacc[t0][0], sacc[t0][1], sacc[t0][2], sacc[t0][3],
                           sacc[t1][0], sacc[t1][1], sacc[t1][2], sacc[t1][3] };
            float hi[8], lo[8];
#pragma unroll
            for (int x = 0; x < 8; x++) {
                __nv_bfloat16 hb = __float2bfloat16(p[x]);
                hi[x] = __bfloat162float(hb);
                lo[x] = p[x] - hi[x];
            }
            phi[kc][0] = pack_bf16(hi[0], hi[1]);
            phi[kc][1] = pack_bf16(hi[2], hi[3]);
            phi[kc][2] = pack_bf16(hi[4], hi[5]);
            phi[kc][3] = pack_bf16(hi[6], hi[7]);
            plo[kc][0] = pack_bf16(lo[0], lo[1]);
            plo[kc][1] = pack_bf16(lo[2], lo[3]);
            plo[kc][2] = pack_bf16(lo[4], lo[5]);
            plo[kc][3] = pack_bf16(lo[6], lo[7]);
        }

        // O += P @ V  (3 products)
#pragma unroll
        for (int kc = 0; kc < 4; kc++) {
#pragma unroll
            for (int jd = 0; jd < 8; jd++) {
                int r = kc * 16 + a_roff;
                int c = jd * 2 + a_csub;
                uint32_t off = r * 256 + ((c ^ (r & 7)) << 4);
                uint32_t vh2[4], vl2[4];
                ldsm_x4_t(vh2, Vh + off);
                ldsm_x4_t(vl2, Vl + off);
                mma_bf16(oacc[jd * 2], phi[kc], vh2);
                mma_bf16(oacc[jd * 2], phi[kc], vl2);
                mma_bf16(oacc[jd * 2], plo[kc], vh2);
                mma_bf16(oacc[jd * 2 + 1], phi[kc], vh2 + 2);
                mma_bf16(oacc[jd * 2 + 1], phi[kc], vl2 + 2);
                mma_bf16(oacc[jd * 2 + 1], plo[kc], vh2 + 2);
            }
        }
    }

    // Epilogue: ctx = O / l -> split bf16
    float inv0 = 1.f / l0, inv1 = 1.f / l1;
    size_t tr0 = tok0 + w * 16 + g;
    size_t tr1 = tr0 + 8;
#pragma unroll
    for (int jd = 0; jd < 16; jd++) {
        int col = h * HDIM + jd * 8 + tig * 2;
        float v00 = oacc[jd][0] * inv0, v01 = oacc[jd][1] * inv0;
        float v10 = oacc[jd][2] * inv1, v11 = oacc[jd][3] * inv1;
        __nv_bfloat16 h00 = __float2bfloat16(v00);
        __nv_bfloat16 h01 = __float2bfloat16(v01);
        __nv_bfloat16 h10 = __float2bfloat16(v10);
        __nv_bfloat16 h11 = __float2bfloat16(v11);
        *(uint32_t*)&ctx_hi[tr0 * EMB + col] = pack_bf16(v00, v01);
        *(uint32_t*)&ctx_hi[tr1 * EMB + col] = pack_bf16(v10, v11);
        *(uint32_t*)&ctx_lo[tr0 * EMB + col] =
            pack_bf16(v00 - __bfloat162float(h00), v01 - __bfloat162float(h01));
        *(uint32_t*)&ctx_lo[tr1 * EMB + col] =
            pack_bf16(v10 - __bfloat162float(h10), v11 - __bfloat162float(h11));
    }
}

// ---------------------------------------------------------------------------
// Launch
// ---------------------------------------------------------------------------
extern "C" void kernel_launch(void* const* d_in, const int* in_sizes, int n_in,
                              void* d_out, int out_size)
{
    const float* hidden = (const float*)d_in[0];
    const float* wqkv   = (const float*)d_in[1];
    const float* bqkv   = (const float*)d_in[2];
    const float* wproj  = (const float*)d_in[3];
    const float* bproj  = (const float*)d_in[4];
    float* out = (float*)d_out;

    __nv_bfloat16 *hid_hi, *hid_lo, *wqkvt_hi, *wqkvt_lo;
    __nv_bfloat16 *wprojt_hi, *wprojt_lo, *qkv_hi, *qkv_lo, *ctx_hi, *ctx_lo;
    cudaGetSymbolAddress((void**)&hid_hi, g_hid_hi);
    cudaGetSymbolAddress((void**)&hid_lo, g_hid_lo);
    cudaGetSymbolAddress((void**)&wqkvt_hi, g_wqkvt_hi);
    cudaGetSymbolAddress((void**)&wqkvt_lo, g_wqkvt_lo);
    cudaGetSymbolAddress((void**)&wprojt_hi, g_wprojt_hi);
    cudaGetSymbolAddress((void**)&wprojt_lo, g_wprojt_lo);
    cudaGetSymbolAddress((void**)&qkv_hi, g_qkv_hi);
    cudaGetSymbolAddress((void**)&qkv_lo, g_qkv_lo);
    cudaGetSymbolAddress((void**)&ctx_hi, g_ctx_hi);
    cudaGetSymbolAddress((void**)&ctx_lo, g_ctx_lo);

    cudaFuncSetAttribute(gemm_mma_kernel,
                         cudaFuncAttributeMaxDynamicSharedMemorySize,
                         GSMEM_TOTAL);
    cudaFuncSetAttribute(flash_attn_mma_kernel,
                         cudaFuncAttributeMaxDynamicSharedMemorySize,
                         AT_SMEM);

    // 0) Split-convert hidden; transpose+split weights
    {
        int n4 = TOTAL * EMB / 4;
        split_convert_kernel<<<(n4 + 255) / 256, 256>>>(hidden, hid_hi, hid_lo, n4);
        dim3 blk(32, 8);
        transpose_split_kernel<<<dim3(E3 / 32, EMB / 32), blk>>>(
            wqkv, wqkvt_hi, wqkvt_lo, EMB, E3);
        transpose_split_kernel<<<dim3(EMB / 32, EMB / 32), blk>>>(
            wproj, wprojt_hi, wprojt_lo, EMB, EMB);
    }
    // 1) QKV GEMM -> split bf16 qkv (bias folded in)
    {
        dim3 grid(E3 / 128, TOTAL / 128);
        gemm_mma_kernel<<<grid, 256, GSMEM_TOTAL>>>(
            hid_hi, hid_lo, wqkvt_hi, wqkvt_lo, bqkv,
            nullptr, qkv_hi, qkv_lo, TOTAL, E3, EMB, 1);
    }
    // 2) Flash attention (mma) -> split bf16 ctx
    {
        dim3 grid(SEQ / 64, BATCH * HEADS);
        flash_attn_mma_kernel<<<grid, 128, AT_SMEM>>>(
            qkv_hi, qkv_lo, ctx_hi, ctx_lo);
    }
    // 3) Proj GEMM -> fp32 out
    {
        dim3 grid(EMB / 128, TOTAL / 128);
        gemm_mma_kernel<<<grid, 256, GSMEM_TOTAL>>>(
            ctx_hi, ctx_lo, wprojt_hi, wprojt_lo, bproj,
            out, nullptr, nullptr, TOTAL, EMB, EMB, 0);
    }
}

// round 7
// speedup vs baseline: 3.6432x; 1.0274x over previous
#include <cuda_runtime.h>
#include <cuda_bf16.h>
#include <math.h>
#include <stdint.h>

// Problem constants (fixed by dataset)
#define BATCH 4
#define SEQ   1024
#define HEADS 16
#define HDIM  128
#define EMB   (HEADS * HDIM)        // 2048
#define TOTAL (BATCH * SEQ)         // 4096
#define E3    (3 * EMB)             // 6144

// ---------------------------------------------------------------------------
// Device scratch (allocation-free rule: __device__ globals)
// ---------------------------------------------------------------------------
__device__ __nv_bfloat16 g_hid_hi[(size_t)TOTAL * EMB];
__device__ __nv_bfloat16 g_hid_lo[(size_t)TOTAL * EMB];
__device__ __nv_bfloat16 g_wqkvt_hi[(size_t)E3 * EMB];   // [N=6144, K=2048]
__device__ __nv_bfloat16 g_wqkvt_lo[(size_t)E3 * EMB];
__device__ __nv_bfloat16 g_wprojt_hi[(size_t)EMB * EMB]; // [N=2048, K=2048]
__device__ __nv_bfloat16 g_wprojt_lo[(size_t)EMB * EMB];
__device__ __nv_bfloat16 g_qkv_hi[(size_t)TOTAL * E3];   // 50.3 MB
__device__ __nv_bfloat16 g_qkv_lo[(size_t)TOTAL * E3];
__device__ __nv_bfloat16 g_ctx_hi[(size_t)TOTAL * EMB];
__device__ __nv_bfloat16 g_ctx_lo[(size_t)TOTAL * EMB];

// ---------------------------------------------------------------------------
// PTX helpers (baseline compute_103-legal: ldmatrix / mma.sync / cp.async)
// ---------------------------------------------------------------------------
__device__ __forceinline__ uint32_t smem_u32(const void* p) {
    uint32_t a;
    asm("{ .reg .u64 t; cvta.to.shared.u64 t, %1; cvt.u32.u64 %0, t; }"
        : "=r"(a) : "l"(p));
    return a;
}
__device__ __forceinline__ void cp_async16(uint32_t dst, const void* src) {
    asm volatile("cp.async.cg.shared.global [%0], [%1], 16;"
                 :: "r"(dst), "l"(src) : "memory");
}
#define CP_COMMIT() asm volatile("cp.async.commit_group;" ::: "memory")
#define CP_WAIT(n)  asm volatile("cp.async.wait_group %0;" :: "n"(n) : "memory")

__device__ __forceinline__ void ldsm_x4(uint32_t* r, uint32_t addr) {
    asm volatile("ldmatrix.sync.aligned.m8n8.x4.shared.b16 {%0,%1,%2,%3}, [%4];"
                 : "=r"(r[0]), "=r"(r[1]), "=r"(r[2]), "=r"(r[3]) : "r"(addr));
}
__device__ __forceinline__ void ldsm_x4_t(uint32_t* r, uint32_t addr) {
    asm volatile("ldmatrix.sync.aligned.m8n8.x4.trans.shared.b16 {%0,%1,%2,%3}, [%4];"
                 : "=r"(r[0]), "=r"(r[1]), "=r"(r[2]), "=r"(r[3]) : "r"(addr));
}
__device__ __forceinline__ void mma_bf16(float* d, const uint32_t* a,
                                         const uint32_t* b) {
    asm volatile(
        "mma.sync.aligned.m16n8k16.row.col.f32.bf16.bf16.f32 "
        "{%0,%1,%2,%3}, {%4,%5,%6,%7}, {%8,%9}, {%0,%1,%2,%3};"
        : "+f"(d[0]), "+f"(d[1]), "+f"(d[2]), "+f"(d[3])
        : "r"(a[0]), "r"(a[1]), "r"(a[2]), "r"(a[3]), "r"(b[0]), "r"(b[1]));
}
__device__ __forceinline__ uint32_t pack_bf16(float x, float y) {
    __nv_bfloat162 t = __floats2bfloat162_rn(x, y);
    return *(uint32_t*)&t;
}

// ---------------------------------------------------------------------------
// Split-convert: X (fp32) -> hi/lo bf16 (same layout)
// ---------------------------------------------------------------------------
__global__ void split_convert_kernel(const float* __restrict__ X,
                                     __nv_bfloat16* __restrict__ H,
                                     __nv_bfloat16* __restrict__ L, int n4)
{
    int i = blockIdx.x * blockDim.x + threadIdx.x;
    if (i >= n4) return;
    float4 v = ((const float4*)X)[i];
    float vs[4] = {v.x, v.y, v.z, v.w};
    __nv_bfloat16 h[4], l[4];
#pragma unroll
    for (int c = 0; c < 4; c++) {
        h[c] = __float2bfloat16(vs[c]);
        l[c] = __float2bfloat16(vs[c] - __bfloat162float(h[c]));
    }
    *(uint2*)(H + i * 4) = *(uint2*)h;
    *(uint2*)(L + i * 4) = *(uint2*)l;
}

// ---------------------------------------------------------------------------
// Transpose + split: X[K,N] fp32 row-major -> T[N,K] hi/lo bf16
// ---------------------------------------------------------------------------
__global__ void transpose_split_kernel(const float* __restrict__ X,
                                       __nv_bfloat16* __restrict__ TH,
                                       __nv_bfloat16* __restrict__ TL,
                                       int K, int N)
{
    __shared__ float tile[32][33];
    int n0 = blockIdx.x * 32, k0 = blockIdx.y * 32;
    int tx = threadIdx.x, ty = threadIdx.y;
#pragma unroll
    for (int i = 0; i < 4; i++)
        tile[ty + i * 8][tx] = X[(size_t)(k0 + ty + i * 8) * N + n0 + tx];
    __syncthreads();
#pragma unroll
    for (int i = 0; i < 4; i++) {
        int n = n0 + ty + i * 8;
        int k = k0 + tx;
        float v = tile[tx][ty + i * 8];
        __nv_bfloat16 hi = __float2bfloat16(v);
        __nv_bfloat16 lo = __float2bfloat16(v - __bfloat162float(hi));
        TH[(size_t)n * K + k] = hi;
        TL[(size_t)n * K + k] = lo;
    }
}

// ---------------------------------------------------------------------------
// bf16-split GEMM via mma.sync: C = (Ahi+Alo) @ (Bhi+Blo)^T + bias
// A[M,K], B[N,K] row-major bf16. BM=BN=128, BK=32. 256 threads, 8 warps.
// 3-stage cp.async ring, ONE __syncthreads per K-chunk.
// mode 0: write fp32 Cf. mode 1: write split bf16 Ch/Cl.
// ---------------------------------------------------------------------------
#define GS_BUF   8192
#define GS_STAGE 32768
#define GS_NSTG  3
#define GSMEM_TOTAL (GS_NSTG * GS_STAGE)   // 96 KB

__device__ __forceinline__ void gemm_load_stage(
    uint32_t sbase, const __nv_bfloat16* __restrict__ Ahi,
    const __nv_bfloat16* __restrict__ Alo,
    const __nv_bfloat16* __restrict__ Bhi,
    const __nv_bfloat16* __restrict__ Blo,
    int m0, int n0, int K, int k0, int tid)
{
    const __nv_bfloat16* bufs[4] = {Ahi, Alo, Bhi, Blo};
#pragma unroll
    for (int i = 0; i < 8; i++) {
        const int buf = i >> 1;
        const int cid = ((i & 1) << 8) + tid;
        const int r = cid >> 2;
        const int c = cid & 3;
        const int row = ((buf < 2) ? m0 : n0) + r;
        uint32_t dst = sbase + buf * GS_BUF + r * 64 +
                       ((c ^ ((r >> 1) & 3)) << 4);
        cp_async16(dst, bufs[buf] + (size_t)row * K + k0 + c * 8);
    }
}

__global__ __launch_bounds__(256) void gemm_mma_kernel(
    const __nv_bfloat16* __restrict__ Ahi, const __nv_bfloat16* __restrict__ Alo,
    const __nv_bfloat16* __restrict__ Bhi, const __nv_bfloat16* __restrict__ Blo,
    const float* __restrict__ bias, float* __restrict__ Cf,
    __nv_bfloat16* __restrict__ Ch, __nv_bfloat16* __restrict__ Cl,
    int M, int N, int K, int mode)
{
    extern __shared__ char smem[];
    const uint32_t sb = smem_u32(smem);
    const int tid = threadIdx.x;
    const int lane = tid & 31;
    const int wid = tid >> 5;
    const int warp_m = wid & 1;
    const int warp_n = wid >> 1;
    const int m0 = blockIdx.y * 128;
    const int n0 = blockIdx.x * 128;

    const int sub = lane >> 3;
    const int lane8 = lane & 7;
    const int a_roff = ((sub & 1) << 3) + lane8;
    const int a_csub = sub >> 1;
    const int b_noff = (((sub >> 1) & 1) << 3) + lane8;
    const int b_csub = sub & 1;

    float acc[4][4][4];
#pragma unroll
    for (int i = 0; i < 4; i++)
#pragma unroll
        for (int j = 0; j < 4; j++)
#pragma unroll
            for (int k = 0; k < 4; k++) acc[i][j][k] = 0.f;

    const int NC = K / 32;   // 64
    // Prologue: stages 0 and 1 in flight
    gemm_load_stage(sb,            Ahi, Alo, Bhi, Blo, m0, n0, K, 0,  tid);
    CP_COMMIT();
    gemm_load_stage(sb + GS_STAGE, Ahi, Alo, Bhi, Blo, m0, n0, K, 32, tid);
    CP_COMMIT();

    int slot = 0;       // slot of stage c
    int wslot = 2;      // slot to write stage c+2
    for (int c = 0; c < NC; c++) {
        if (c + 1 < NC) { CP_WAIT(1); } else { CP_WAIT(0); }
        __syncthreads();   // stage c visible; everyone done computing c-1
        if (c + 2 < NC) {
            gemm_load_stage(sb + wslot * GS_STAGE, Ahi, Alo, Bhi, Blo,
                            m0, n0, K, (c + 2) * 32, tid);
            CP_COMMIT();
        }
        const uint32_t st = sb + slot * GS_STAGE;
        slot = (slot + 1 == GS_NSTG) ? 0 : slot + 1;
        wslot = (wslot + 1 == GS_NSTG) ? 0 : wslot + 1;

#pragma unroll
        for (int ks = 0; ks < 2; ks++) {
            uint32_t ah[4][4], al[4][4];
#pragma unroll
            for (int im = 0; im < 4; im++) {
                int r = warp_m * 64 + im * 16 + a_roff;
                int cc = ks * 2 + a_csub;
                uint32_t off = r * 64 + ((cc ^ ((r >> 1) & 3)) << 4);
                ldsm_x4(ah[im], st + off);
                ldsm_x4(al[im], st + GS_BUF + off);
            }
            uint32_t bh[4][2], bl[4][2];
#pragma unroll
            for (int in2 = 0; in2 < 2; in2++) {
                int n = warp_n * 32 + in2 * 16 + b_noff;
                int cc = ks * 2 + b_csub;
                uint32_t off = n * 64 + ((cc ^ ((n >> 1) & 3)) << 4);
                uint32_t t[4];
                ldsm_x4(t, st + 2 * GS_BUF + off);
                bh[in2 * 2][0] = t[0]; bh[in2 * 2][1] = t[1];
                bh[in2 * 2 + 1][0] = t[2]; bh[in2 * 2 + 1][1] = t[3];
                ldsm_x4(t, st + 3 * GS_BUF + off);
                bl[in2 * 2][0] = t[0]; bl[in2 * 2][1] = t[1];
                bl[in2 * 2 + 1][0] = t[2]; bl[in2 * 2 + 1][1] = t[3];
            }
#pragma unroll
            for (int im = 0; im < 4; im++)
#pragma unroll
                for (int in = 0; in < 4; in++) {
                    mma_bf16(acc[im][in], ah[im], bh[in]);
                    mma_bf16(acc[im][in], ah[im], bl[in]);
                    mma_bf16(acc[im][in], al[im], bh[in]);
                }
        }
    }

    // Epilogue
    const int groupID = lane >> 2;
    const int tig = lane & 3;
#pragma unroll
    for (int im = 0; im < 4; im++) {
        int row0 = m0 + warp_m * 64 + im * 16 + groupID;
#pragma unroll
        for (int in = 0; in < 4; in++) {
            int col = n0 + warp_n * 32 + in * 8 + tig * 2;
            float2 bv = *(const float2*)&bias[col];
            float v00 = acc[im][in][0] + bv.x, v01 = acc[im][in][1] + bv.y;
            float v10 = acc[im][in][2] + bv.x, v11 = acc[im][in][3] + bv.y;
            if (mode == 0) {
                *(float2*)&Cf[(size_t)row0 * N + col] = make_float2(v00, v01);
                *(float2*)&Cf[(size_t)(row0 + 8) * N + col] = make_float2(v10, v11);
            } else {
                __nv_bfloat16 h00 = __float2bfloat16(v00);
                __nv_bfloat16 h01 = __float2bfloat16(v01);
                __nv_bfloat16 h10 = __float2bfloat16(v10);
                __nv_bfloat16 h11 = __float2bfloat16(v11);
                *(uint32_t*)&Ch[(size_t)row0 * N + col] = pack_bf16(v00, v01);
                *(uint32_t*)&Ch[(size_t)(row0 + 8) * N + col] = pack_bf16(v10, v11);
                *(uint32_t*)&Cl[(size_t)row0 * N + col] =
                    pack_bf16(v00 - __bfloat162float(h00),
                              v01 - __bfloat162float(h01));
                *(uint32_t*)&Cl[(size_t)(row0 + 8) * N + col] =
                    pack_bf16(v10 - __bfloat162float(h10),
                              v11 - __bfloat162float(h11));
            }
        }
    }
}

// ---------------------------------------------------------------------------
// Flash attention (causal) via mma.sync. BM=64 q rows, BN=64 keys, 4 warps.
// Double-buffered K/V tiles: Q 16K + 2 x (Ks 16K | Vh 16K | Vl 16K) = 112 KB.
// ---------------------------------------------------------------------------
#define AT_STAGE 49152
#define AT_SMEM (16384 + 2 * AT_STAGE)   // 114688

__global__ __launch_bounds__(128) void flash_attn_mma_kernel(
    const __nv_bfloat16* __restrict__ qkv_hi,
    const __nv_bfloat16* __restrict__ qkv_lo,
    __nv_bfloat16* __restrict__ ctx_hi,
    __nv_bfloat16* __restrict__ ctx_lo)
{
    extern __shared__ char smem[];
    const uint32_t sb = smem_u32(smem);
    const uint32_t Qs = sb;

    const int qt = blockIdx.x;            // 0..15
    const int bh = blockIdx.y;            // 0..63
    const int b = bh >> 4, h = bh & 15;
    const int q0 = qt * 64;
    const int tid = threadIdx.x;
    const int lane = tid & 31;
    const int w = tid >> 5;

    const int sub = lane >> 3, lane8 = lane & 7;
    const int a_roff = ((sub & 1) << 3) + lane8;
    const int a_csub = sub >> 1;
    const int b_noff = (((sub >> 1) & 1) << 3) + lane8;
    const int b_csub = sub & 1;
    const int g = lane >> 2, tig = lane & 3;

    const size_t tok0 = (size_t)b * SEQ + q0;
    const size_t kbase = (size_t)b * SEQ;

    // Prologue: Q tile + K/V tile 0 in one group
#pragma unroll
    for (int i = 0; i < 8; i++) {
        int idx = tid + i * 128;
        int r = idx >> 4, c = idx & 15;
        uint32_t dst = Qs + r * 256 + ((c ^ (r & 7)) << 4);
        cp_async16(dst, qkv_hi + (tok0 + r) * E3 + h * HDIM + c * 8);
    }
    {
        const uint32_t S0 = sb + 16384;
#pragma unroll
        for (int i = 0; i < 8; i++) {
            int idx = tid + i * 128;
            int r = idx >> 4, c = idx & 15;
            uint32_t sw = r * 256 + ((c ^ (r & 7)) << 4);
            size_t base = (kbase + r) * E3 + h * HDIM + c * 8;
            cp_async16(S0 + sw, qkv_hi + base + EMB);
            cp_async16(S0 + 16384 + sw, qkv_hi + base + 2 * EMB);
            cp_async16(S0 + 32768 + sw, qkv_lo + base + 2 * EMB);
        }
    }
    CP_COMMIT();

    uint32_t qa[8][4];
    float oacc[16][4];
#pragma unroll
    for (int t = 0; t < 16; t++)
#pragma unroll
        for (int k = 0; k < 4; k++) oacc[t][k] = 0.f;
    float m0 = -INFINITY, m1 = -INFINITY, l0 = 0.f, l1 = 0.f;

    const float sc = 0.08838834764831845f;
    const int row0 = q0 + w * 16 + g;
    const int row1 = row0 + 8;

    for (int kt = 0; kt <= qt; kt++) {
        CP_WAIT(0);
        __syncthreads();   // tile kt visible; prev compute done -> other buf free

        if (kt < qt) {     // prefetch tile kt+1 into the other buffer
            const uint32_t S1 = sb + 16384 + ((kt + 1) & 1) * AT_STAGE;
            size_t kb0 = kbase + (size_t)(kt + 1) * 64;
#pragma unroll
            for (int i = 0; i < 8; i++) {
                int idx = tid + i * 128;
                int r = idx >> 4, c = idx & 15;
                uint32_t sw = r * 256 + ((c ^ (r & 7)) << 4);
                size_t base = (kb0 + r) * E3 + h * HDIM + c * 8;
                cp_async16(S1 + sw, qkv_hi + base + EMB);
                cp_async16(S1 + 16384 + sw, qkv_hi + base + 2 * EMB);
                cp_async16(S1 + 32768 + sw, qkv_lo + base + 2 * EMB);
            }
            CP_COMMIT();
        }
        if (kt == 0) {     // Q fragments resident for whole kernel
#pragma unroll
            for (int kc = 0; kc < 8; kc++) {
                int r = w * 16 + a_roff;
                int c = kc * 2 + a_csub;
                ldsm_x4(qa[kc], Qs + r * 256 + ((c ^ (r & 7)) << 4));
            }
        }

        const uint32_t Ks = sb + 16384 + (kt & 1) * AT_STAGE;
        const uint32_t Vh = Ks + 16384;
        const uint32_t Vl = Ks + 32768;

        // S = Q K^T (hi only)
        float sacc[8][4];
#pragma unroll
        for (int j = 0; j < 8; j++)
#pragma unroll
            for (int k = 0; k < 4; k++) sacc[j][k] = 0.f;
#pragma unroll
        for (int kc = 0; kc < 8; kc++) {
#pragma unroll
            for (int jn = 0; jn < 4; jn++) {
                int r = jn * 16 + b_noff;
                int c = kc * 2 + b_csub;
                uint32_t kb[4];
                ldsm_x4(kb, Ks + r * 256 + ((c ^ (r & 7)) << 4));
                mma_bf16(sacc[jn * 2],     qa[kc], kb);
                mma_bf16(sacc[jn * 2 + 1], qa[kc], kb + 2);
            }
        }

        // scale + causal mask + row max
        float mx0 = -INFINITY, mx1 = -INFINITY;
#pragma unroll
        for (int j = 0; j < 8; j++) {
            int col = kt * 64 + j * 8 + tig * 2;
            float s0 = sacc[j][0] * sc, s1 = sacc[j][1] * sc;
            float s2 = sacc[j][2] * sc, s3 = sacc[j][3] * sc;
            if (kt == qt) {
                if (col > row0)     s0 = -1e30f;
                if (col + 1 > row0) s1 = -1e30f;
                if (col > row1)     s2 = -1e30f;
                if (col + 1 > row1) s3 = -1e30f;
            }
            sacc[j][0] = s0; sacc[j][1] = s1; sacc[j][2] = s2; sacc[j][3] = s3;
            mx0 = fmaxf(mx0, fmaxf(s0, s1));
            mx1 = fmaxf(mx1, fmaxf(s2, s3));
        }
        mx0 = fmaxf(mx0, __shfl_xor_sync(0xffffffffu, mx0, 1));
        mx0 = fmaxf(mx0, __shfl_xor_sync(0xffffffffu, mx0, 2));
        mx1 = fmaxf(mx1, __shfl_xor_sync(0xffffffffu, mx1, 1));
        mx1 = fmaxf(mx1, __shfl_xor_sync(0xffffffffu, mx1, 2));

        float mn0 = fmaxf(m0, mx0), mn1 = fmaxf(m1, mx1);
        float al0 = __expf(m0 - mn0), al1 = __expf(m1 - mn1);
        m0 = mn0; m1 = mn1;

        float sum0 = 0.f, sum1 = 0.f;
#pragma unroll
        for (int j = 0; j < 8; j++) {
            float p0 = __expf(sacc[j][0] - mn0);
            float p1 = __expf(sacc[j][1] - mn0);
            float p2 = __expf(sacc[j][2] - mn1);
            float p3 = __expf(sacc[j][3] - mn1);
            sacc[j][0] = p0; sacc[j][1] = p1; sacc[j][2] = p2; sacc[j][3] = p3;
            sum0 += p0 + p1; sum1 += p2 + p3;
        }
        sum0 += __shfl_xor_sync(0xffffffffu, sum0, 1);
        sum0 += __shfl_xor_sync(0xffffffffu, sum0, 2);
        sum1 += __shfl_xor_sync(0xffffffffu, sum1, 1);
        sum1 += __shfl_xor_sync(0xffffffffu, sum1, 2);
        l0 = l0 * al0 + sum0;
        l1 = l1 * al1 + sum1;

        // rescale O
#pragma unroll
        for (int t = 0; t < 16; t++) {
            oacc[t][0] *= al0; oacc[t][1] *= al0;
            oacc[t][2] *= al1; oacc[t][3] *= al1;
        }

        // pack P fragments (hi/lo split)
        uint32_t phi[4][4], plo[4][4];
#pragma unroll
        for (int kc = 0; kc < 4; kc++) {
            int t0 = kc * 2, t1 = kc * 2 + 1;
            float p[8] = { sacc[t0][0], sacc[t0][1], sacc[t0][2], sacc[t0][3],
                           sacc[t1][0], sacc[t1][1], sacc[t1][2], sacc[t1][3] };
            float hi[8], lo[8];
#pragma unroll
            for (int x = 0; x < 8; x++) {
                __nv_bfloat16 hb = __float2bfloat16(p[x]);
                hi[x] = __bfloat162float(hb);
                lo[x] = p[x] - hi[x];
            }
            phi[kc][0] = pack_bf16(hi[0], hi[1]);
            phi[kc][1] = pack_bf16(hi[2], hi[3]);
            phi[kc][2] = pack_bf16(hi[4], hi[5]);
            phi[kc][3] = pack_bf16(hi[6], hi[7]);
            plo[kc][0] = pack_bf16(lo[0], lo[1]);
            plo[kc][1] = pack_bf16(lo[2], lo[3]);
            plo[kc][2] = pack_bf16(lo[4], lo[5]);
            plo[kc][3] = pack_bf16(lo[6], lo[7]);
        }

        // O += P @ V  (3 products)
#pragma unroll
        for (int kc = 0; kc < 4; kc++) {
#pragma unroll
            for (int jd = 0; jd < 8; jd++) {
                int r = kc * 16 + a_roff;
                int c = jd * 2 + a_csub;
                uint32_t off = r * 256 + ((c ^ (r & 7)) << 4);
                uint32_t vh2[4], vl2[4];
                ldsm_x4_t(vh2, Vh + off);
                ldsm_x4_t(vl2, Vl + off);
                mma_bf16(oacc[jd * 2], phi[kc], vh2);
                mma_bf16(oacc[jd * 2], phi[kc], vl2);
                mma_bf16(oacc[jd * 2], plo[kc], vh2);
                mma_bf16(oacc[jd * 2 + 1], phi[kc], vh2 + 2);
                mma_bf16(oacc[jd * 2 + 1], phi[kc], vl2 + 2);
                mma_bf16(oacc[jd * 2 + 1], plo[kc], vh2 + 2);
            }
        }
    }

    // Epilogue: ctx = O / l -> split bf16
    float inv0 = 1.f / l0, inv1 = 1.f / l1;
    size_t tr0 = tok0 + w * 16 + g;
    size_t tr1 = tr0 + 8;
#pragma unroll
    for (int jd = 0; jd < 16; jd++) {
        int col = h * HDIM + jd * 8 + tig * 2;
        float v00 = oacc[jd][0] * inv0, v01 = oacc[jd][1] * inv0;
        float v10 = oacc[jd][2] * inv1, v11 = oacc[jd][3] * inv1;
        __nv_bfloat16 h00 = __float2bfloat16(v00);
        __nv_bfloat16 h01 = __float2bfloat16(v01);
        __nv_bfloat16 h10 = __float2bfloat16(v10);
        __nv_bfloat16 h11 = __float2bfloat16(v11);
        *(uint32_t*)&ctx_hi[tr0 * EMB + col] = pack_bf16(v00, v01);
        *(uint32_t*)&ctx_hi[tr1 * EMB + col] = pack_bf16(v10, v11);
        *(uint32_t*)&ctx_lo[tr0 * EMB + col] =
            pack_bf16(v00 - __bfloat162float(h00), v01 - __bfloat162float(h01));
        *(uint32_t*)&ctx_lo[tr1 * EMB + col] =
            pack_bf16(v10 - __bfloat162float(h10), v11 - __bfloat162float(h11));
    }
}

// ---------------------------------------------------------------------------
// Launch
// ---------------------------------------------------------------------------
extern "C" void kernel_launch(void* const* d_in, const int* in_sizes, int n_in,
                              void* d_out, int out_size)
{
    const float* hidden = (const float*)d_in[0];
    const float* wqkv   = (const float*)d_in[1];
    const float* bqkv   = (const float*)d_in[2];
    const float* wproj  = (const float*)d_in[3];
    const float* bproj  = (const float*)d_in[4];
    float* out = (float*)d_out;

    __nv_bfloat16 *hid_hi, *hid_lo, *wqkvt_hi, *wqkvt_lo;
    __nv_bfloat16 *wprojt_hi, *wprojt_lo, *qkv_hi, *qkv_lo, *ctx_hi, *ctx_lo;
    cudaGetSymbolAddress((void**)&hid_hi, g_hid_hi);
    cudaGetSymbolAddress((void**)&hid_lo, g_hid_lo);
    cudaGetSymbolAddress((void**)&wqkvt_hi, g_wqkvt_hi);
    cudaGetSymbolAddress((void**)&wqkvt_lo, g_wqkvt_lo);
    cudaGetSymbolAddress((void**)&wprojt_hi, g_wprojt_hi);
    cudaGetSymbolAddress((void**)&wprojt_lo, g_wprojt_lo);
    cudaGetSymbolAddress((void**)&qkv_hi, g_qkv_hi);
    cudaGetSymbolAddress((void**)&qkv_lo, g_qkv_lo);
    cudaGetSymbolAddress((void**)&ctx_hi, g_ctx_hi);
    cudaGetSymbolAddress((void**)&ctx_lo, g_ctx_lo);

    cudaFuncSetAttribute(gemm_mma_kernel,
                         cudaFuncAttributeMaxDynamicSharedMemorySize,
                         GSMEM_TOTAL);
    cudaFuncSetAttribute(flash_attn_mma_kernel,
                         cudaFuncAttributeMaxDynamicSharedMemorySize,
                         AT_SMEM);

    // 0) Split-convert hidden; transpose+split weights
    {
        int n4 = TOTAL * EMB / 4;
        split_convert_kernel<<<(n4 + 255) / 256, 256>>>(hidden, hid_hi, hid_lo, n4);
        dim3 blk(32, 8);
        transpose_split_kernel<<<dim3(E3 / 32, EMB / 32), blk>>>(
            wqkv, wqkvt_hi, wqkvt_lo, EMB, E3);
        transpose_split_kernel<<<dim3(EMB / 32, EMB / 32), blk>>>(
            wproj, wprojt_hi, wprojt_lo, EMB, EMB);
    }
    // 1) QKV GEMM -> split bf16 qkv (bias folded in)
    {
        dim3 grid(E3 / 128, TOTAL / 128);
        gemm_mma_kernel<<<grid, 256, GSMEM_TOTAL>>>(
            hid_hi, hid_lo, wqkvt_hi, wqkvt_lo, bqkv,
            nullptr, qkv_hi, qkv_lo, TOTAL, E3, EMB, 1);
    }
    // 2) Flash attention (mma) -> split bf16 ctx
    {
        dim3 grid(SEQ / 64, BATCH * HEADS);
        flash_attn_mma_kernel<<<grid, 128, AT_SMEM>>>(
            qkv_hi, qkv_lo, ctx_hi, ctx_lo);
    }
    // 3) Proj GEMM -> fp32 out
    {
        dim3 grid(EMB / 128, TOTAL / 128);
        gemm_mma_kernel<<<grid, 256, GSMEM_TOTAL>>>(
            ctx_hi, ctx_lo, wprojt_hi, wprojt_lo, bproj,
            out, nullptr, nullptr, TOTAL, EMB, EMB, 0);
    }
}

// round 8
// speedup vs baseline: 5.0133x; 1.3760x over previous
#include <cuda_runtime.h>
#include <cuda_bf16.h>
#include <cuda_fp16.h>
#include <math.h>
#include <stdint.h>

// Problem constants (fixed by dataset)
#define BATCH 4
#define SEQ   1024
#define HEADS 16
#define HDIM  128
#define EMB   (HEADS * HDIM)        // 2048
#define TOTAL (BATCH * SEQ)         // 4096
#define E3    (3 * EMB)             // 6144

// All split tensors are stored SCALED by 1024 so the fp16 'lo' parts stay
// normal (no subnormal flush risk). Consumers unscale by 2^-20 (two scaled
// operands) in their fp32 epilogues.
#define SCALE     1024.0f
#define INV_S2    (1.0f / 1048576.0f)

// ---------------------------------------------------------------------------
// Device scratch (allocation-free rule: __device__ globals)
// ---------------------------------------------------------------------------
__device__ __half g_hid_hi[(size_t)TOTAL * EMB];          // 1024*hidden (hi only)
__device__ __half g_wqkvt_hi[(size_t)E3 * EMB];           // [N=6144,K=2048]
__device__ __half g_wqkvt_lo[(size_t)E3 * EMB];
__device__ __half g_wprojt_hi[(size_t)EMB * EMB];         // [N=2048,K=2048]
__device__ __half g_wprojt_lo[(size_t)EMB * EMB];
__device__ __half g_qkv_hi[(size_t)TOTAL * E3];           // 1024*qkv
__device__ __half g_qkv_lo[(size_t)TOTAL * E3];           // (lo used for V)
__device__ __half g_ctx_hi[(size_t)TOTAL * EMB];          // 1024*ctx (hi only)

// ---------------------------------------------------------------------------
// PTX helpers (baseline compute_103-legal: ldmatrix / mma.sync / cp.async)
// ---------------------------------------------------------------------------
__device__ __forceinline__ uint32_t smem_u32(const void* p) {
    uint32_t a;
    asm("{ .reg .u64 t; cvta.to.shared.u64 t, %1; cvt.u32.u64 %0, t; }"
        : "=r"(a) : "l"(p));
    return a;
}
__device__ __forceinline__ void cp_async16(uint32_t dst, const void* src) {
    asm volatile("cp.async.cg.shared.global [%0], [%1], 16;"
                 :: "r"(dst), "l"(src) : "memory");
}
#define CP_COMMIT() asm volatile("cp.async.commit_group;" ::: "memory")
#define CP_WAIT(n)  asm volatile("cp.async.wait_group %0;" :: "n"(n) : "memory")

__device__ __forceinline__ void ldsm_x4(uint32_t* r, uint32_t addr) {
    asm volatile("ldmatrix.sync.aligned.m8n8.x4.shared.b16 {%0,%1,%2,%3}, [%4];"
                 : "=r"(r[0]), "=r"(r[1]), "=r"(r[2]), "=r"(r[3]) : "r"(addr));
}
__device__ __forceinline__ void ldsm_x4_t(uint32_t* r, uint32_t addr) {
    asm volatile("ldmatrix.sync.aligned.m8n8.x4.trans.shared.b16 {%0,%1,%2,%3}, [%4];"
                 : "=r"(r[0]), "=r"(r[1]), "=r"(r[2]), "=r"(r[3]) : "r"(addr));
}
__device__ __forceinline__ void mma_f16(float* d, const uint32_t* a,
                                        const uint32_t* b) {
    asm volatile(
        "mma.sync.aligned.m16n8k16.row.col.f32.f16.f16.f32 "
        "{%0,%1,%2,%3}, {%4,%5,%6,%7}, {%8,%9}, {%0,%1,%2,%3};"
        : "+f"(d[0]), "+f"(d[1]), "+f"(d[2]), "+f"(d[3])
        : "r"(a[0]), "r"(a[1]), "r"(a[2]), "r"(a[3]), "r"(b[0]), "r"(b[1]));
}
__device__ __forceinline__ uint32_t pack_h2(float x, float y) {
    __half2 t = __floats2half2_rn(x, y);
    return *(uint32_t*)&t;
}

// ---------------------------------------------------------------------------
// Convert (hi only): H = fp16(1024 * X)
// ---------------------------------------------------------------------------
__global__ void convert_hi_kernel(const float* __restrict__ X,
                                  __half* __restrict__ H, int n4)
{
    int i = blockIdx.x * blockDim.x + threadIdx.x;
    if (i >= n4) return;
    float4 v = ((const float4*)X)[i];
    uint32_t o[2];
    o[0] = pack_h2(v.x * SCALE, v.y * SCALE);
    o[1] = pack_h2(v.z * SCALE, v.w * SCALE);
    *(uint2*)(H + i * 4) = *(uint2*)o;
}

// ---------------------------------------------------------------------------
// Transpose + split: X[K,N] fp32 -> T[N,K] fp16 hi/lo of (1024*X)
// ---------------------------------------------------------------------------
__global__ void transpose_split_kernel(const float* __restrict__ X,
                                       __half* __restrict__ TH,
                                       __half* __restrict__ TL,
                                       int K, int N)
{
    __shared__ float tile[32][33];
    int n0 = blockIdx.x * 32, k0 = blockIdx.y * 32;
    int tx = threadIdx.x, ty = threadIdx.y;
#pragma unroll
    for (int i = 0; i < 4; i++)
        tile[ty + i * 8][tx] = X[(size_t)(k0 + ty + i * 8) * N + n0 + tx];
    __syncthreads();
#pragma unroll
    for (int i = 0; i < 4; i++) {
        int n = n0 + ty + i * 8;
        int k = k0 + tx;
        float v = tile[tx][ty + i * 8] * SCALE;
        __half hi = __float2half_rn(v);
        __half lo = __float2half_rn(v - __half2float(hi));
        TH[(size_t)n * K + k] = hi;
        TL[(size_t)n * K + k] = lo;
    }
}

// ---------------------------------------------------------------------------
// fp16 2-product GEMM via mma.sync: C = Ah @ (Bh+Bl)^T * 2^-20 + bias
// A hi-only [M,K], B hi/lo [N,K], all scaled by 1024. BM=BN=128, BK=32.
// 256 threads, 8 warps (2x4), warp tile 64x32. 4-stage cp.async ring.
// Stage: Ah | Bh | Bl = 3 x 8KB = 24KB.
// mode 0: fp32 Cf.  mode 1: split fp16 Ch/Cl of 1024*C.
// ---------------------------------------------------------------------------
#define GS_BUF   8192
#define GS_STAGE 24576
#define GS_NSTG  4
#define GSMEM_TOTAL (GS_NSTG * GS_STAGE)   // 96 KB

__device__ __forceinline__ void gemm_load_stage(
    uint32_t sbase, const __half* __restrict__ Ah,
    const __half* __restrict__ Bh, const __half* __restrict__ Bl,
    int m0, int n0, int K, int k0, int tid)
{
    const __half* bufs[3] = {Ah, Bh, Bl};
#pragma unroll
    for (int i = 0; i < 6; i++) {
        const int idx = tid + i * 256;        // 0..1535
        const int buf = idx >> 9;             // 0..2
        const int r = (idx >> 2) & 127;
        const int c = idx & 3;
        const int row = ((buf == 0) ? m0 : n0) + r;
        uint32_t dst = sbase + buf * GS_BUF + r * 64 +
                       ((c ^ ((r >> 1) & 3)) << 4);
        cp_async16(dst, bufs[buf] + (size_t)row * K + k0 + c * 8);
    }
}

__global__ __launch_bounds__(256) void gemm_mma_kernel(
    const __half* __restrict__ Ah,
    const __half* __restrict__ Bh, const __half* __restrict__ Bl,
    const float* __restrict__ bias, float* __restrict__ Cf,
    __half* __restrict__ Ch, __half* __restrict__ Cl,
    int M, int N, int K, int mode)
{
    extern __shared__ char smem[];
    const uint32_t sb = smem_u32(smem);
    const int tid = threadIdx.x;
    const int lane = tid & 31;
    const int wid = tid >> 5;
    const int warp_m = wid & 1;
    const int warp_n = wid >> 1;
    const int m0 = blockIdx.y * 128;
    const int n0 = blockIdx.x * 128;

    const int sub = lane >> 3;
    const int lane8 = lane & 7;
    const int a_roff = ((sub & 1) << 3) + lane8;
    const int a_csub = sub >> 1;
    const int b_noff = (((sub >> 1) & 1) << 3) + lane8;
    const int b_csub = sub & 1;

    float acc[4][4][4];
#pragma unroll
    for (int i = 0; i < 4; i++)
#pragma unroll
        for (int j = 0; j < 4; j++)
#pragma unroll
            for (int k = 0; k < 4; k++) acc[i][j][k] = 0.f;

    const int NC = K / 32;   // 64
    // Prologue: stages 0..2 in flight
    gemm_load_stage(sb,                Ah, Bh, Bl, m0, n0, K, 0,  tid); CP_COMMIT();
    gemm_load_stage(sb + GS_STAGE,     Ah, Bh, Bl, m0, n0, K, 32, tid); CP_COMMIT();
    gemm_load_stage(sb + 2 * GS_STAGE, Ah, Bh, Bl, m0, n0, K, 64, tid); CP_COMMIT();

    int slot = 0;
    for (int c = 0; c < NC; c++) {
        if (c + 3 <= NC)      { CP_WAIT(2); }
        else if (c + 2 == NC) { CP_WAIT(1); }
        else                  { CP_WAIT(0); }
        __syncthreads();   // stage c visible; slot (c+3)&3 free
        if (c + 3 < NC) {
            gemm_load_stage(sb + ((c + 3) & 3) * GS_STAGE, Ah, Bh, Bl,
                            m0, n0, K, (c + 3) * 32, tid);
            CP_COMMIT();
        }
        const uint32_t st = sb + slot * GS_STAGE;
        slot = (slot + 1) & 3;

#pragma unroll
        for (int ks = 0; ks < 2; ks++) {
            uint32_t ah[4][4];
#pragma unroll
            for (int im = 0; im < 4; im++) {
                int r = warp_m * 64 + im * 16 + a_roff;
                int cc = ks * 2 + a_csub;
                uint32_t off = r * 64 + ((cc ^ ((r >> 1) & 3)) << 4);
                ldsm_x4(ah[im], st + off);
            }
            uint32_t bh[4][2], bl[4][2];
#pragma unroll
            for (int in2 = 0; in2 < 2; in2++) {
                int n = warp_n * 32 + in2 * 16 + b_noff;
                int cc = ks * 2 + b_csub;
                uint32_t off = n * 64 + ((cc ^ ((n >> 1) & 3)) << 4);
                uint32_t t[4];
                ldsm_x4(t, st + GS_BUF + off);
                bh[in2 * 2][0] = t[0]; bh[in2 * 2][1] = t[1];
                bh[in2 * 2 + 1][0] = t[2]; bh[in2 * 2 + 1][1] = t[3];
                ldsm_x4(t, st + 2 * GS_BUF + off);
                bl[in2 * 2][0] = t[0]; bl[in2 * 2][1] = t[1];
                bl[in2 * 2 + 1][0] = t[2]; bl[in2 * 2 + 1][1] = t[3];
            }
#pragma unroll
            for (int im = 0; im < 4; im++)
#pragma unroll
                for (int in = 0; in < 4; in++) {
                    mma_f16(acc[im][in], ah[im], bh[in]);
                    mma_f16(acc[im][in], ah[im], bl[in]);
                }
        }
    }

    // Epilogue: unscale 2^-20, add bias
    const int groupID = lane >> 2;
    const int tig = lane & 3;
#pragma unroll
    for (int im = 0; im < 4; im++) {
        int row0 = m0 + warp_m * 64 + im * 16 + groupID;
#pragma unroll
        for (int in = 0; in < 4; in++) {
            int col = n0 + warp_n * 32 + in * 8 + tig * 2;
            float2 bv = *(const float2*)&bias[col];
            float v00 = acc[im][in][0] * INV_S2 + bv.x;
            float v01 = acc[im][in][1] * INV_S2 + bv.y;
            float v10 = acc[im][in][2] * INV_S2 + bv.x;
            float v11 = acc[im][in][3] * INV_S2 + bv.y;
            if (mode == 0) {
                *(float2*)&Cf[(size_t)row0 * N + col] = make_float2(v00, v01);
                *(float2*)&Cf[(size_t)(row0 + 8) * N + col] = make_float2(v10, v11);
            } else {
                float s00 = v00 * SCALE, s01 = v01 * SCALE;
                float s10 = v10 * SCALE, s11 = v11 * SCALE;
                __half h00 = __float2half_rn(s00);
                __half h01 = __float2half_rn(s01);
                __half h10 = __float2half_rn(s10);
                __half h11 = __float2half_rn(s11);
                *(uint32_t*)&Ch[(size_t)row0 * N + col] = pack_h2(s00, s01);
                *(uint32_t*)&Ch[(size_t)(row0 + 8) * N + col] = pack_h2(s10, s11);
                *(uint32_t*)&Cl[(size_t)row0 * N + col] =
                    pack_h2(s00 - __half2float(h00), s01 - __half2float(h01));
                *(uint32_t*)&Cl[(size_t)(row0 + 8) * N + col] =
                    pack_h2(s10 - __half2float(h10), s11 - __half2float(h11));
            }
        }
    }
}

// ---------------------------------------------------------------------------
// Flash attention (causal) via fp16 mma.sync. BM=64 q rows, BN=64 keys,
// 4 warps. S = Qh*Kh (single product, logits tiny). O += Ph*(Vh+Vl).
// Double-buffered K/V: Q 16K + 2 x (Kh|Vh|Vl 48K) = 112 KB.
// qkv splits hold 1024*value; ctx_hi gets 1024*ctx = oacc/l directly.
// ---------------------------------------------------------------------------
#define AT_STAGE 49152
#define AT_SMEM (16384 + 2 * AT_STAGE)   // 114688

__global__ __launch_bounds__(128) void flash_attn_mma_kernel(
    const __half* __restrict__ qkv_hi,
    const __half* __restrict__ qkv_lo,
    __half* __restrict__ ctx_hi)
{
    extern __shared__ char smem[];
    const uint32_t sb = smem_u32(smem);
    const uint32_t Qs = sb;

    const int qt = blockIdx.x;            // 0..15
    const int bh = blockIdx.y;            // 0..63
    const int b = bh >> 4, h = bh & 15;
    const int q0 = qt * 64;
    const int tid = threadIdx.x;
    const int lane = tid & 31;
    const int w = tid >> 5;

    const int sub = lane >> 3, lane8 = lane & 7;
    const int a_roff = ((sub & 1) << 3) + lane8;
    const int a_csub = sub >> 1;
    const int b_noff = (((sub >> 1) & 1) << 3) + lane8;
    const int b_csub = sub & 1;
    const int g = lane >> 2, tig = lane & 3;

    const size_t tok0 = (size_t)b * SEQ + q0;
    const size_t kbase = (size_t)b * SEQ;

    // Prologue: Q tile + K/V tile 0
#pragma unroll
    for (int i = 0; i < 8; i++) {
        int idx = tid + i * 128;
        int r = idx >> 4, c = idx & 15;
        uint32_t dst = Qs + r * 256 + ((c ^ (r & 7)) << 4);
        cp_async16(dst, qkv_hi + (tok0 + r) * E3 + h * HDIM + c * 8);
    }
    {
        const uint32_t S0 = sb + 16384;
#pragma unroll
        for (int i = 0; i < 8; i++) {
            int idx = tid + i * 128;
            int r = idx >> 4, c = idx & 15;
            uint32_t sw = r * 256 + ((c ^ (r & 7)) << 4);
            size_t base = (kbase + r) * E3 + h * HDIM + c * 8;
            cp_async16(S0 + sw, qkv_hi + base + EMB);
            cp_async16(S0 + 16384 + sw, qkv_hi + base + 2 * EMB);
            cp_async16(S0 + 32768 + sw, qkv_lo + base + 2 * EMB);
        }
    }
    CP_COMMIT();

    uint32_t qa[8][4];
    float oacc[16][4];
#pragma unroll
    for (int t = 0; t < 16; t++)
#pragma unroll
        for (int k = 0; k < 4; k++) oacc[t][k] = 0.f;
    float m0 = -INFINITY, m1 = -INFINITY, l0 = 0.f, l1 = 0.f;

    const float sc2 = 0.08838834764831845f * INV_S2;  // undo 1024^2 scaling
    const int row0 = q0 + w * 16 + g;
    const int row1 = row0 + 8;

    for (int kt = 0; kt <= qt; kt++) {
        CP_WAIT(0);
        __syncthreads();

        if (kt < qt) {     // prefetch tile kt+1
            const uint32_t S1 = sb + 16384 + ((kt + 1) & 1) * AT_STAGE;
            size_t kb0 = kbase + (size_t)(kt + 1) * 64;
#pragma unroll
            for (int i = 0; i < 8; i++) {
                int idx = tid + i * 128;
                int r = idx >> 4, c = idx & 15;
                uint32_t sw = r * 256 + ((c ^ (r & 7)) << 4);
                size_t base = (kb0 + r) * E3 + h * HDIM + c * 8;
                cp_async16(S1 + sw, qkv_hi + base + EMB);
                cp_async16(S1 + 16384 + sw, qkv_hi + base + 2 * EMB);
                cp_async16(S1 + 32768 + sw, qkv_lo + base + 2 * EMB);
            }
            CP_COMMIT();
        }
        if (kt == 0) {
#pragma unroll
            for (int kc = 0; kc < 8; kc++) {
                int r = w * 16 + a_roff;
                int c = kc * 2 + a_csub;
                ldsm_x4(qa[kc], Qs + r * 256 + ((c ^ (r & 7)) << 4));
            }
        }

        const uint32_t Ks = sb + 16384 + (kt & 1) * AT_STAGE;
        const uint32_t Vh = Ks + 16384;
        const uint32_t Vl = Ks + 32768;

        // S = Q K^T (hi x hi)
        float sacc[8][4];
#pragma unroll
        for (int j = 0; j < 8; j++)
#pragma unroll
            for (int k = 0; k < 4; k++) sacc[j][k] = 0.f;
#pragma unroll
        for (int kc = 0; kc < 8; kc++) {
#pragma unroll
            for (int jn = 0; jn < 4; jn++) {
                int r = jn * 16 + b_noff;
                int c = kc * 2 + b_csub;
                uint32_t kb[4];
                ldsm_x4(kb, Ks + r * 256 + ((c ^ (r & 7)) << 4));
                mma_f16(sacc[jn * 2],     qa[kc], kb);
                mma_f16(sacc[jn * 2 + 1], qa[kc], kb + 2);
            }
        }

        // scale + causal mask + row max
        float mx0 = -INFINITY, mx1 = -INFINITY;
#pragma unroll
        for (int j = 0; j < 8; j++) {
            int col = kt * 64 + j * 8 + tig * 2;
            float s0 = sacc[j][0] * sc2, s1 = sacc[j][1] * sc2;
            float s2 = sacc[j][2] * sc2, s3 = sacc[j][3] * sc2;
            if (kt == qt) {
                if (col > row0)     s0 = -1e30f;
                if (col + 1 > row0) s1 = -1e30f;
                if (col > row1)     s2 = -1e30f;
                if (col + 1 > row1) s3 = -1e30f;
            }
            sacc[j][0] = s0; sacc[j][1] = s1; sacc[j][2] = s2; sacc[j][3] = s3;
            mx0 = fmaxf(mx0, fmaxf(s0, s1));
            mx1 = fmaxf(mx1, fmaxf(s2, s3));
        }
        mx0 = fmaxf(mx0, __shfl_xor_sync(0xffffffffu, mx0, 1));
        mx0 = fmaxf(mx0, __shfl_xor_sync(0xffffffffu, mx0, 2));
        mx1 = fmaxf(mx1, __shfl_xor_sync(0xffffffffu, mx1, 1));
        mx1 = fmaxf(mx1, __shfl_xor_sync(0xffffffffu, mx1, 2));

        float mn0 = fmaxf(m0, mx0), mn1 = fmaxf(m1, mx1);
        float al0 = __expf(m0 - mn0), al1 = __expf(m1 - mn1);
        m0 = mn0; m1 = mn1;

        float sum0 = 0.f, sum1 = 0.f;
#pragma unroll
        for (int j = 0; j < 8; j++) {
            float p0 = __expf(sacc[j][0] - mn0);
            float p1 = __expf(sacc[j][1] - mn0);
            float p2 = __expf(sacc[j][2] - mn1);
            float p3 = __expf(sacc[j][3] - mn1);
            sacc[j][0] = p0; sacc[j][1] = p1; sacc[j][2] = p2; sacc[j][3] = p3;
            sum0 += p0 + p1; sum1 += p2 + p3;
        }
        sum0 += __shfl_xor_sync(0xffffffffu, sum0, 1);
        sum0 += __shfl_xor_sync(0xffffffffu, sum0, 2);
        sum1 += __shfl_xor_sync(0xffffffffu, sum1, 1);
        sum1 += __shfl_xor_sync(0xffffffffu, sum1, 2);
        l0 = l0 * al0 + sum0;
        l1 = l1 * al1 + sum1;

        // rescale O
#pragma unroll
        for (int t = 0; t < 16; t++) {
            oacc[t][0] *= al0; oacc[t][1] *= al0;
            oacc[t][2] *= al1; oacc[t][3] *= al1;
        }

        // pack P (hi only, fp16)
        uint32_t phi[4][4];
#pragma unroll
        for (int kc = 0; kc < 4; kc++) {
            int t0 = kc * 2, t1 = kc * 2 + 1;
            phi[kc][0] = pack_h2(sacc[t0][0], sacc[t0][1]);
            phi[kc][1] = pack_h2(sacc[t0][2], sacc[t0][3]);
            phi[kc][2] = pack_h2(sacc[t1][0], sacc[t1][1]);
            phi[kc][3] = pack_h2(sacc[t1][2], sacc[t1][3]);
        }

        // O += P @ (Vh + Vl)
#pragma unroll
        for (int kc = 0; kc < 4; kc++) {
#pragma unroll
            for (int jd = 0; jd < 8; jd++) {
                int r = kc * 16 + a_roff;
                int c = jd * 2 + a_csub;
                uint32_t off = r * 256 + ((c ^ (r & 7)) << 4);
                uint32_t vh2[4], vl2[4];
                ldsm_x4_t(vh2, Vh + off);
                ldsm_x4_t(vl2, Vl + off);
                mma_f16(oacc[jd * 2], phi[kc], vh2);
                mma_f16(oacc[jd * 2], phi[kc], vl2);
                mma_f16(oacc[jd * 2 + 1], phi[kc], vh2 + 2);
                mma_f16(oacc[jd * 2 + 1], phi[kc], vl2 + 2);
            }
        }
    }

    // Epilogue: ctx_hi = oacc / l  (== 1024 * ctx, since V was scaled)
    float inv0 = 1.f / l0, inv1 = 1.f / l1;
    size_t tr0 = tok0 + w * 16 + g;
    size_t tr1 = tr0 + 8;
#pragma unroll
    for (int jd = 0; jd < 16; jd++) {
        int col = h * HDIM + jd * 8 + tig * 2;
        *(uint32_t*)&ctx_hi[tr0 * EMB + col] =
            pack_h2(oacc[jd][0] * inv0, oacc[jd][1] * inv0);
        *(uint32_t*)&ctx_hi[tr1 * EMB + col] =
            pack_h2(oacc[jd][2] * inv1, oacc[jd][3] * inv1);
    }
}

// ---------------------------------------------------------------------------
// Launch
// ---------------------------------------------------------------------------
extern "C" void kernel_launch(void* const* d_in, const int* in_sizes, int n_in,
                              void* d_out, int out_size)
{
    const float* hidden = (const float*)d_in[0];
    const float* wqkv   = (const float*)d_in[1];
    const float* bqkv   = (const float*)d_in[2];
    const float* wproj  = (const float*)d_in[3];
    const float* bproj  = (const float*)d_in[4];
    float* out = (float*)d_out;

    __half *hid_hi, *wqkvt_hi, *wqkvt_lo, *wprojt_hi, *wprojt_lo;
    __half *qkv_hi, *qkv_lo, *ctx_hi;
    cudaGetSymbolAddress((void**)&hid_hi, g_hid_hi);
    cudaGetSymbolAddress((void**)&wqkvt_hi, g_wqkvt_hi);
    cudaGetSymbolAddress((void**)&wqkvt_lo, g_wqkvt_lo);
    cudaGetSymbolAddress((void**)&wprojt_hi, g_wprojt_hi);
    cudaGetSymbolAddress((void**)&wprojt_lo, g_wprojt_lo);
    cudaGetSymbolAddress((void**)&qkv_hi, g_qkv_hi);
    cudaGetSymbolAddress((void**)&qkv_lo, g_qkv_lo);
    cudaGetSymbolAddress((void**)&ctx_hi, g_ctx_hi);

    cudaFuncSetAttribute(gemm_mma_kernel,
                         cudaFuncAttributeMaxDynamicSharedMemorySize,
                         GSMEM_TOTAL);
    cudaFuncSetAttribute(flash_attn_mma_kernel,
                         cudaFuncAttributeMaxDynamicSharedMemorySize,
                         AT_SMEM);

    // 0) Convert hidden (hi only); transpose+split weights
    {
        int n4 = TOTAL * EMB / 4;
        convert_hi_kernel<<<(n4 + 255) / 256, 256>>>(hidden, hid_hi, n4);
        dim3 blk(32, 8);
        transpose_split_kernel<<<dim3(E3 / 32, EMB / 32), blk>>>(
            wqkv, wqkvt_hi, wqkvt_lo, EMB, E3);
        transpose_split_kernel<<<dim3(EMB / 32, EMB / 32), blk>>>(
            wproj, wprojt_hi, wprojt_lo, EMB, EMB);
    }
    // 1) QKV GEMM -> split fp16 qkv (bias folded in, scaled by 1024)
    {
        dim3 grid(E3 / 128, TOTAL / 128);
        gemm_mma_kernel<<<grid, 256, GSMEM_TOTAL>>>(
            hid_hi, wqkvt_hi, wqkvt_lo, bqkv,
            nullptr, qkv_hi, qkv_lo, TOTAL, E3, EMB, 1);
    }
    // 2) Flash attention -> ctx_hi (scaled by 1024)
    {
        dim3 grid(SEQ / 64, BATCH * HEADS);
        flash_attn_mma_kernel<<<grid, 128, AT_SMEM>>>(
            qkv_hi, qkv_lo, ctx_hi);
    }
    // 3) Proj GEMM -> fp32 out
    {
        dim3 grid(EMB / 128, TOTAL / 128);
        gemm_mma_kernel<<<grid, 256, GSMEM_TOTAL>>>(
            ctx_hi, wprojt_hi, wprojt_lo, bproj,
            out, nullptr, nullptr, TOTAL, EMB, EMB, 0);
    }
}